// round 14
// baseline (speedup 1.0000x reference)
#include <cuda_runtime.h>
#include <cuda_fp16.h>
#include <cstdint>

#define BATCH 2
#define LQ    21760
#define TTOK  (BATCH * LQ)     // 43520
#define DMODEL 256
#define NH    8
#define DH    32
#define NL    4
#define NP    4
#define MLPD  1024

__device__ __constant__ int c_H[4]     = {128, 64, 32, 16};
__device__ __constant__ int c_W[4]     = {128, 64, 32, 16};
__device__ __constant__ int c_start[4] = {0, 16384, 20480, 21504};

// fp16 activation scratch
__device__ __half g_xln_h [TTOK * DMODEL];
__device__ __half g_q_h   [TTOK * DMODEL];
__device__ __half g_val_h [TTOK * DMODEL];
__device__ __half g_samp_h[TTOK * DMODEL];
__device__ __half g_y_h   [TTOK * DMODEL];
__device__ __half g_h_h   [TTOK * MLPD];
// fp32 scratch
__device__ float g_oa  [TTOK * 384];
__device__ float g_src2[TTOK * DMODEL];
// transposed fp16 weights [N][K]
__device__ __half g_wvalT [DMODEL * DMODEL];
__device__ __half g_woaT  [384 * DMODEL];
__device__ __half g_woutT [DMODEL * DMODEL];
__device__ __half g_wfc1T [MLPD * DMODEL];
__device__ __half g_wfc2T [DMODEL * MLPD];
__device__ float  g_boa   [384];

// ---------------------------------------------------------------------------
__device__ __forceinline__ void cpasync16(void* smem_dst, const void* gsrc) {
    unsigned dst = (unsigned)__cvta_generic_to_shared(smem_dst);
    asm volatile("cp.async.cg.shared.global [%0], [%1], 16;\n" :: "r"(dst), "l"(gsrc));
}
#define CP_COMMIT() asm volatile("cp.async.commit_group;\n" ::: "memory")
#define CP_WAIT0()  asm volatile("cp.async.wait_group 0;\n" ::: "memory")
#define CP_WAIT1()  asm volatile("cp.async.wait_group 1;\n" ::: "memory")

__device__ __forceinline__ unsigned smem_u32(const void* p) {
    return (unsigned)__cvta_generic_to_shared(p);
}
__device__ __forceinline__ void ldsm_x4(unsigned addr, unsigned& r0, unsigned& r1,
                                        unsigned& r2, unsigned& r3) {
    asm volatile("ldmatrix.sync.aligned.m8n8.x4.shared.b16 {%0,%1,%2,%3}, [%4];\n"
                 : "=r"(r0), "=r"(r1), "=r"(r2), "=r"(r3) : "r"(addr));
}
#define MMA16816(d, a, b0, b1) \
    asm volatile( \
        "mma.sync.aligned.m16n8k16.row.col.f32.f16.f16.f32 " \
        "{%0,%1,%2,%3}, {%4,%5,%6,%7}, {%8,%9}, {%0,%1,%2,%3};\n" \
        : "+f"((d)[0]), "+f"((d)[1]), "+f"((d)[2]), "+f"((d)[3]) \
        : "r"((a)[0]), "r"((a)[1]), "r"((a)[2]), "r"((a)[3]), "r"(b0), "r"(b1))

#define HS_STRIDE 40
#define HS_TILE   (128 * HS_STRIDE)

// ---------------------------------------------------------------------------
// Weight transpose+convert
// ---------------------------------------------------------------------------
struct TDesc { const float* in; __half* out; int K; int N; };
struct TDescs { TDesc d[6]; };

__global__ __launch_bounds__(256) void transpose_all(TDescs td)
{
    TDesc w = td.d[blockIdx.z];
    int n0 = blockIdx.x * 32, k0 = blockIdx.y * 32;
    if (n0 >= w.N || k0 >= w.K) return;
    __shared__ float tile[32][33];
    int tx = threadIdx.x, ty = threadIdx.y;
#pragma unroll
    for (int dy = 0; dy < 32; dy += 8)
        tile[ty + dy][tx] = w.in[(size_t)(k0 + ty + dy) * w.N + n0 + tx];
    __syncthreads();
#pragma unroll
    for (int dy = 0; dy < 32; dy += 8)
        w.out[(size_t)(n0 + ty + dy) * w.K + k0 + tx] = __float2half(tile[tx][ty + dy]);
}

__global__ void concat_bias(const float* __restrict__ boff,
                            const float* __restrict__ battn,
                            float* __restrict__ out)
{
    int i = threadIdx.x;
    if (i < 384) out[i] = (i < 256) ? boff[i] : battn[i - 256];
}

// ---------------------------------------------------------------------------
// LayerNorm (LN1): one warp per token; also writes q = ln + pos.
// ---------------------------------------------------------------------------
__global__ __launch_bounds__(256) void ln_kernel(
    const float* __restrict__ x, const float* __restrict__ pos,
    const float* __restrict__ g, const float* __restrict__ b,
    __half* __restrict__ out, __half* __restrict__ qout)
{
    int warp = threadIdx.x >> 5, lane = threadIdx.x & 31;
    int t = blockIdx.x * 8 + warp;
    if (t >= TTOK) return;

    const float4* xr = (const float4*)(x + (size_t)t * DMODEL);
    float4 v0 = xr[lane * 2 + 0];
    float4 v1 = xr[lane * 2 + 1];
    float vals[8] = {v0.x, v0.y, v0.z, v0.w, v1.x, v1.y, v1.z, v1.w};

    float s = 0.f;
#pragma unroll
    for (int i = 0; i < 8; i++) s += vals[i];
#pragma unroll
    for (int o = 16; o; o >>= 1) s += __shfl_xor_sync(0xffffffffu, s, o);
    float mu = s * (1.0f / 256.0f);

    float vs = 0.f;
#pragma unroll
    for (int i = 0; i < 8; i++) { float d = vals[i] - mu; vs += d * d; }
#pragma unroll
    for (int o = 16; o; o >>= 1) vs += __shfl_xor_sync(0xffffffffu, vs, o);
    float rstd = rsqrtf(vs * (1.0f / 256.0f) + 1e-6f);

    int c0 = lane * 8;
    float o8[8];
#pragma unroll
    for (int i = 0; i < 8; i++) {
        int c = c0 + i;
        o8[i] = (vals[i] - mu) * rstd * g[c] + b[c];
    }
    __half2* orow = (__half2*)(out + (size_t)t * DMODEL);
#pragma unroll
    for (int i = 0; i < 4; i++)
        orow[lane * 4 + i] = __floats2half2_rn(o8[2 * i], o8[2 * i + 1]);

    if (qout) {
        const float4* pr = (const float4*)(pos + (size_t)t * DMODEL);
        float4 p0 = pr[lane * 2 + 0];
        float4 p1 = pr[lane * 2 + 1];
        float p8[8] = {p0.x, p0.y, p0.z, p0.w, p1.x, p1.y, p1.z, p1.w};
        __half2* qrow = (__half2*)(qout + (size_t)t * DMODEL);
#pragma unroll
        for (int i = 0; i < 4; i++)
            qrow[lane * 4 + i] = __floats2half2_rn(o8[2 * i] + p8[2 * i], o8[2 * i + 1] + p8[2 * i + 1]);
    }
}

// ---------------------------------------------------------------------------
// fp32-acc GEMM (BK=32, 2 CTA/SM) — fc1/fc2.
// ---------------------------------------------------------------------------
template<bool RELU, bool RES, typename OutT>
__global__ __launch_bounds__(256, 2) void hgemm(
    const __half* __restrict__ A, const __half* __restrict__ Wt,
    const float* __restrict__ bias, const float* __restrict__ res,
    OutT* __restrict__ C, int M, int N, int K)
{
    __shared__ __half As[2 * HS_TILE];
    __shared__ __half Bs[2 * HS_TILE];

    int tid  = threadIdx.x;
    int lane = tid & 31, warp = tid >> 5;
    int g  = lane >> 2, tg = lane & 3;
    int wm = (warp & 3) * 32;
    int wn = (warp >> 2) * 64;
    int rb = blockIdx.y * 128, cb = blockIdx.x * 128;

    int lr = tid >> 2, lc = tid & 3;
    int a_row = (lane & 15), a_k = (lane >> 4) * 8;
    int b_row = (lane & 7) + ((lane >> 4) << 3), b_k = ((lane >> 3) & 1) * 8;

    float acc[2][8][4];
#pragma unroll
    for (int mi = 0; mi < 2; mi++)
#pragma unroll
        for (int ni = 0; ni < 8; ni++)
#pragma unroll
            for (int v = 0; v < 4; v++) acc[mi][ni][v] = 0.f;

    auto issue = [&](int kt, int buf) {
        int k0 = kt * 32;
#pragma unroll
        for (int i = 0; i < 2; i++) {
            int r = lr + 64 * i;
            cpasync16(As + buf * HS_TILE + r * HS_STRIDE + lc * 8,
                      A + (size_t)(rb + r) * K + k0 + lc * 8);
            cpasync16(Bs + buf * HS_TILE + r * HS_STRIDE + lc * 8,
                      Wt + (size_t)(cb + r) * K + k0 + lc * 8);
        }
    };

    int nt = K >> 5;
    issue(0, 0);
    CP_COMMIT();

    for (int kt = 0; kt < nt; kt++) {
        CP_WAIT0();
        __syncthreads();
        if (kt + 1 < nt) { issue(kt + 1, (kt + 1) & 1); CP_COMMIT(); }

        const __half* Ab = As + (kt & 1) * HS_TILE;
        const __half* Bb = Bs + (kt & 1) * HS_TILE;

#pragma unroll
        for (int ks = 0; ks < 2; ks++) {
            int k0 = ks * 16;
            unsigned a[2][4];
#pragma unroll
            for (int mi = 0; mi < 2; mi++) {
                unsigned addr = smem_u32(Ab + (wm + mi * 16 + a_row) * HS_STRIDE + k0 + a_k);
                ldsm_x4(addr, a[mi][0], a[mi][1], a[mi][2], a[mi][3]);
            }
#pragma unroll
            for (int nj = 0; nj < 4; nj++) {
                unsigned b0, b1, b2, b3;
                unsigned addr = smem_u32(Bb + (wn + nj * 16 + b_row) * HS_STRIDE + k0 + b_k);
                ldsm_x4(addr, b0, b1, b2, b3);
#pragma unroll
                for (int mi = 0; mi < 2; mi++) {
                    MMA16816(acc[mi][2 * nj], a[mi], b0, b1);
                    MMA16816(acc[mi][2 * nj + 1], a[mi], b2, b3);
                }
            }
        }
        __syncthreads();
    }

#pragma unroll
    for (int mi = 0; mi < 2; mi++) {
        int r0 = rb + wm + mi * 16 + g;
#pragma unroll
        for (int ni = 0; ni < 8; ni++) {
            int cc = cb + wn + ni * 8 + 2 * tg;
            float bv0 = bias[cc], bv1 = bias[cc + 1];
            float v0 = acc[mi][ni][0] + bv0;
            float v1 = acc[mi][ni][1] + bv1;
            float v2 = acc[mi][ni][2] + bv0;
            float v3 = acc[mi][ni][3] + bv1;
            size_t o0 = (size_t)r0 * N + cc;
            size_t o1 = (size_t)(r0 + 8) * N + cc;
            if (RES) {
                v0 += res[o0]; v1 += res[o0 + 1];
                v2 += res[o1]; v3 += res[o1 + 1];
            }
            if (RELU) {
                v0 = fmaxf(v0, 0.f); v1 = fmaxf(v1, 0.f);
                v2 = fmaxf(v2, 0.f); v3 = fmaxf(v3, 0.f);
            }
            if (sizeof(OutT) == 2) {
                *(__half2*)((__half*)C + o0) = __floats2half2_rn(v0, v1);
                *(__half2*)((__half*)C + o1) = __floats2half2_rn(v2, v3);
            } else {
                *(float2*)((float*)C + o0) = make_float2(v0, v1);
                *(float2*)((float*)C + o1) = make_float2(v2, v3);
            }
        }
    }
}

// ---------------------------------------------------------------------------
// Fused val+oa GEMM (validated).
// ---------------------------------------------------------------------------
__global__ __launch_bounds__(256, 2) void dual_gemm(
    const __half* __restrict__ xln, const __half* __restrict__ q,
    const __half* __restrict__ wvalT, const __half* __restrict__ woaT,
    const float* __restrict__ bval, const float* __restrict__ boa,
    __half* __restrict__ val_out, float* __restrict__ oa_out)
{
    __shared__ __half As[2 * HS_TILE];
    __shared__ __half Bs[2 * HS_TILE];

    bool isVal = blockIdx.x < 2;
    const __half* A    = isVal ? xln : q;
    const __half* Wt   = isVal ? wvalT : woaT;
    const float*  bias = isVal ? bval : boa;
    int N  = isVal ? 256 : 384;
    int cb = isVal ? (int)blockIdx.x * 128 : ((int)blockIdx.x - 2) * 128;
    const int K = 256;

    int tid  = threadIdx.x;
    int lane = tid & 31, warp = tid >> 5;
    int g  = lane >> 2, tg = lane & 3;
    int wm = (warp & 3) * 32;
    int wn = (warp >> 2) * 64;
    int rb = blockIdx.y * 128;

    int lr = tid >> 2, lc = tid & 3;
    int a_row = (lane & 15), a_k = (lane >> 4) * 8;
    int b_row = (lane & 7) + ((lane >> 4) << 3), b_k = ((lane >> 3) & 1) * 8;

    float acc[2][8][4];
#pragma unroll
    for (int mi = 0; mi < 2; mi++)
#pragma unroll
        for (int ni = 0; ni < 8; ni++)
#pragma unroll
            for (int v = 0; v < 4; v++) acc[mi][ni][v] = 0.f;

    auto issue = [&](int kt, int buf) {
        int k0 = kt * 32;
#pragma unroll
        for (int i = 0; i < 2; i++) {
            int r = lr + 64 * i;
            cpasync16(As + buf * HS_TILE + r * HS_STRIDE + lc * 8,
                      A + (size_t)(rb + r) * K + k0 + lc * 8);
            cpasync16(Bs + buf * HS_TILE + r * HS_STRIDE + lc * 8,
                      Wt + (size_t)(cb + r) * K + k0 + lc * 8);
        }
    };

    int nt = K >> 5;
    issue(0, 0);
    CP_COMMIT();

    for (int kt = 0; kt < nt; kt++) {
        CP_WAIT0();
        __syncthreads();
        if (kt + 1 < nt) { issue(kt + 1, (kt + 1) & 1); CP_COMMIT(); }

        const __half* Ab = As + (kt & 1) * HS_TILE;
        const __half* Bb = Bs + (kt & 1) * HS_TILE;

#pragma unroll
        for (int ks = 0; ks < 2; ks++) {
            int k0 = ks * 16;
            unsigned a[2][4];
#pragma unroll
            for (int mi = 0; mi < 2; mi++) {
                unsigned addr = smem_u32(Ab + (wm + mi * 16 + a_row) * HS_STRIDE + k0 + a_k);
                ldsm_x4(addr, a[mi][0], a[mi][1], a[mi][2], a[mi][3]);
            }
#pragma unroll
            for (int nj = 0; nj < 4; nj++) {
                unsigned b0, b1, b2, b3;
                unsigned addr = smem_u32(Bb + (wn + nj * 16 + b_row) * HS_STRIDE + k0 + b_k);
                ldsm_x4(addr, b0, b1, b2, b3);
#pragma unroll
                for (int mi = 0; mi < 2; mi++) {
                    MMA16816(acc[mi][2 * nj], a[mi], b0, b1);
                    MMA16816(acc[mi][2 * nj + 1], a[mi], b2, b3);
                }
            }
        }
        __syncthreads();
    }

#pragma unroll
    for (int mi = 0; mi < 2; mi++) {
        int r0 = rb + wm + mi * 16 + g;
#pragma unroll
        for (int ni = 0; ni < 8; ni++) {
            int cc = cb + wn + ni * 8 + 2 * tg;
            float bv0 = bias[cc], bv1 = bias[cc + 1];
            float v0 = acc[mi][ni][0] + bv0;
            float v1 = acc[mi][ni][1] + bv1;
            float v2 = acc[mi][ni][2] + bv0;
            float v3 = acc[mi][ni][3] + bv1;
            size_t o0 = (size_t)r0 * N + cc;
            size_t o1 = (size_t)(r0 + 8) * N + cc;
            if (isVal) {
                *(__half2*)(val_out + o0) = __floats2half2_rn(v0, v1);
                *(__half2*)(val_out + o1) = __floats2half2_rn(v2, v3);
            } else {
                *(float2*)(oa_out + o0) = make_float2(v0, v1);
                *(float2*)(oa_out + o1) = make_float2(v2, v3);
            }
        }
    }
}

// ---------------------------------------------------------------------------
// Fused w_out GEMM + residual + LayerNorm2 (round-9 256-thread version).
// ---------------------------------------------------------------------------
#define GL_STRIDE 40
#define GL_A_H    (128 * GL_STRIDE)
#define GL_B_H    (256 * GL_STRIDE)
#define GL_STG_H  (GL_A_H + GL_B_H)
#define GL_SMEM   (3 * GL_STG_H * 2)    // 92160 bytes

__global__ __launch_bounds__(256, 1) void gemm_ln(
    const __half* __restrict__ A, const __half* __restrict__ Wt,
    const float* __restrict__ bias, const float* __restrict__ res,
    const float* __restrict__ g2, const float* __restrict__ b2,
    float* __restrict__ src2, __half* __restrict__ y)
{
    extern __shared__ __half sh[];
    const int N = 256, K = 256;

    int tid  = threadIdx.x;
    int lane = tid & 31, warp = tid >> 5;
    int g  = lane >> 2, tg = lane & 3;
    int wm = (warp & 1) * 64;
    int wn = (warp >> 1) * 64;
    int wnq = warp >> 1;
    int rb = blockIdx.y * 128;

    int a_row = (lane & 15), a_k = (lane >> 4) * 8;
    int b_row = (lane & 7) + ((lane >> 4) << 3), b_k = ((lane >> 3) & 1) * 8;

    float acc[4][8][4];
#pragma unroll
    for (int mi = 0; mi < 4; mi++)
#pragma unroll
        for (int ni = 0; ni < 8; ni++)
#pragma unroll
            for (int v = 0; v < 4; v++) acc[mi][ni][v] = 0.f;

    const __half* Ab = A + (size_t)rb * K;

    auto issue = [&](int kt, int buf) {
        int k0 = kt * 32;
        __half* st = sh + buf * GL_STG_H;
#pragma unroll
        for (int i = 0; i < 6; i++) {
            int chunk = tid + 256 * i;
            if (chunk < 512) {
                int row = chunk >> 2, c16 = chunk & 3;
                cpasync16(st + row * GL_STRIDE + c16 * 8,
                          Ab + (size_t)row * K + k0 + c16 * 8);
            } else {
                int bc = chunk - 512;
                int row = bc >> 2, c16 = bc & 3;
                cpasync16(st + GL_A_H + row * GL_STRIDE + c16 * 8,
                          Wt + (size_t)row * K + k0 + c16 * 8);
            }
        }
    };

    int nt = K >> 5;
    issue(0, 0); CP_COMMIT();
    issue(1, 1); CP_COMMIT();

    for (int kt = 0; kt < nt; kt++) {
        CP_WAIT1();
        __syncthreads();

        int buf = kt % 3;
        const __half* Abs = sh + buf * GL_STG_H;
        const __half* Bbs = Abs + GL_A_H;

#pragma unroll
        for (int ks = 0; ks < 2; ks++) {
            int k0 = ks * 16;
            unsigned a[4][4];
#pragma unroll
            for (int mi = 0; mi < 4; mi++) {
                unsigned addr = smem_u32(Abs + (wm + mi * 16 + a_row) * GL_STRIDE + k0 + a_k);
                ldsm_x4(addr, a[mi][0], a[mi][1], a[mi][2], a[mi][3]);
            }
#pragma unroll
            for (int nj = 0; nj < 4; nj++) {
                unsigned b0, b1, b2, b3;
                unsigned addr = smem_u32(Bbs + (wn + nj * 16 + b_row) * GL_STRIDE + k0 + b_k);
                ldsm_x4(addr, b0, b1, b2, b3);
#pragma unroll
                for (int mi = 0; mi < 4; mi++) {
                    MMA16816(acc[mi][2 * nj], a[mi], b0, b1);
                    MMA16816(acc[mi][2 * nj + 1], a[mi], b2, b3);
                }
            }
        }
        if (kt + 2 < nt) issue(kt + 2, (kt + 2) % 3);
        CP_COMMIT();
    }

    CP_WAIT0();
    __syncthreads();
    float2* part = (float2*)sh;

#pragma unroll
    for (int mi = 0; mi < 4; mi++) {
        int r0 = rb + wm + mi * 16 + g;
        float s0 = 0.f, q0 = 0.f, s1 = 0.f, q1 = 0.f;
#pragma unroll
        for (int ni = 0; ni < 8; ni++) {
            int cc = wn + ni * 8 + 2 * tg;
            float bv0 = bias[cc], bv1 = bias[cc + 1];
            size_t o0 = (size_t)r0 * N + cc;
            size_t o1 = (size_t)(r0 + 8) * N + cc;
            float v0 = acc[mi][ni][0] + bv0 + res[o0];
            float v1 = acc[mi][ni][1] + bv1 + res[o0 + 1];
            float v2 = acc[mi][ni][2] + bv0 + res[o1];
            float v3 = acc[mi][ni][3] + bv1 + res[o1 + 1];
            acc[mi][ni][0] = v0; acc[mi][ni][1] = v1;
            acc[mi][ni][2] = v2; acc[mi][ni][3] = v3;
            *(float2*)(src2 + o0) = make_float2(v0, v1);
            *(float2*)(src2 + o1) = make_float2(v2, v3);
            s0 += v0 + v1; q0 += v0 * v0 + v1 * v1;
            s1 += v2 + v3; q1 += v2 * v2 + v3 * v3;
        }
#pragma unroll
        for (int o = 1; o < 4; o <<= 1) {
            s0 += __shfl_xor_sync(0xffffffffu, s0, o);
            q0 += __shfl_xor_sync(0xffffffffu, q0, o);
            s1 += __shfl_xor_sync(0xffffffffu, s1, o);
            q1 += __shfl_xor_sync(0xffffffffu, q1, o);
        }
        if (tg == 0) {
            int rl = wm + mi * 16 + g;
            part[rl * 4 + wnq]       = make_float2(s0, q0);
            part[(rl + 8) * 4 + wnq] = make_float2(s1, q1);
        }
    }
    __syncthreads();

#pragma unroll
    for (int mi = 0; mi < 4; mi++) {
        int rl = wm + mi * 16 + g;
        float2 pa0 = part[rl * 4 + 0], pa1 = part[rl * 4 + 1],
               pa2 = part[rl * 4 + 2], pa3 = part[rl * 4 + 3];
        float2 pb0 = part[(rl + 8) * 4 + 0], pb1 = part[(rl + 8) * 4 + 1],
               pb2 = part[(rl + 8) * 4 + 2], pb3 = part[(rl + 8) * 4 + 3];
        float sum0 = pa0.x + pa1.x + pa2.x + pa3.x;
        float sq0  = pa0.y + pa1.y + pa2.y + pa3.y;
        float sum1 = pb0.x + pb1.x + pb2.x + pb3.x;
        float sq1  = pb0.y + pb1.y + pb2.y + pb3.y;
        float mu0 = sum0 * (1.f / 256.f);
        float mu1 = sum1 * (1.f / 256.f);
        float rs0 = rsqrtf(fmaxf(sq0 * (1.f / 256.f) - mu0 * mu0, 0.f) + 1e-6f);
        float rs1 = rsqrtf(fmaxf(sq1 * (1.f / 256.f) - mu1 * mu1, 0.f) + 1e-6f);
        int r0 = rb + rl;
#pragma unroll
        for (int ni = 0; ni < 8; ni++) {
            int cc = wn + ni * 8 + 2 * tg;
            float gg0 = g2[cc], gg1 = g2[cc + 1];
            float bb0 = b2[cc], bb1 = b2[cc + 1];
            float y0 = (acc[mi][ni][0] - mu0) * rs0 * gg0 + bb0;
            float y1 = (acc[mi][ni][1] - mu0) * rs0 * gg1 + bb1;
            float y2 = (acc[mi][ni][2] - mu1) * rs1 * gg0 + bb0;
            float y3 = (acc[mi][ni][3] - mu1) * rs1 * gg1 + bb1;
            *(__half2*)(y + (size_t)r0 * N + cc)       = __floats2half2_rn(y0, y1);
            *(__half2*)(y + (size_t)(r0 + 8) * N + cc) = __floats2half2_rn(y2, y3);
        }
    }
}

// ---------------------------------------------------------------------------
// Deformable attention sampling: round-9 validated body, grid-stride
// persistent blocks (1184 CTAs) to remove wave-transition overhead.
// ---------------------------------------------------------------------------
#define MSDA_BLOCKS 1184

__global__ __launch_bounds__(256) void msda_kernel(
    const __half* __restrict__ val, const float* __restrict__ oa,
    const float* __restrict__ refp, __half* __restrict__ out)
{
    int h = threadIdx.x >> 5;
    int lane = threadIdx.x & 31;
    int hw = lane >> 4, cl = lane & 15;

    for (int t = blockIdx.x; t < TTOK; t += MSDA_BLOCKS) {
        int b = t / LQ;
        const float* oarow = oa + (size_t)t * 384;

        float lg = -1e30f;
        if (lane < 16) lg = oarow[256 + h * 16 + lane];
        float mx = lg;
#pragma unroll
        for (int o = 8; o; o >>= 1) mx = fmaxf(mx, __shfl_xor_sync(0xffffffffu, mx, o));
        float ex = (lane < 16) ? __expf(lg - mx) : 0.f;
        float sm = ex;
#pragma unroll
        for (int o = 8; o; o >>= 1) sm += __shfl_xor_sync(0xffffffffu, sm, o);
        float w = (lane < 16) ? (ex / sm) : 0.f;

        float xf = 0.f, yf = 0.f;
        if (lane < 16) {
            int l = lane >> 2;
            float ox = oarow[h * 32 + lane * 2 + 0];
            float oy = oarow[h * 32 + lane * 2 + 1];
            float Wsf = (float)c_W[l], Hsf = (float)c_H[l];
            float locx = refp[(size_t)t * 8 + l * 2 + 0] + ox / Wsf;
            float locy = refp[(size_t)t * 8 + l * 2 + 1] + oy / Hsf;
            xf = locx * Wsf - 0.5f;
            yf = locy * Hsf - 0.5f;
        }

        float acc0 = 0.f, acc1 = 0.f;
        const __half2* vb = (const __half2*)val + (size_t)b * LQ * 128 + h * 16 + cl;

#pragma unroll
        for (int j = 0; j < 8; j++) {
            int p = 2 * j + hw;
            float xp = __shfl_sync(0xffffffffu, xf, p);
            float yp = __shfl_sync(0xffffffffu, yf, p);
            float wp = __shfl_sync(0xffffffffu, w, p);
            int l = p >> 2;
            int Hs = c_H[l], Ws = c_W[l], st = c_start[l];

            float x0f = floorf(xp), y0f = floorf(yp);
            float lx = xp - x0f, ly = yp - y0f;
            int x0 = (int)x0f, y0 = (int)y0f;

            bool xin0 = (unsigned)x0 < (unsigned)Ws;
            bool xin1 = (unsigned)(x0 + 1) < (unsigned)Ws;
            bool yin0 = (unsigned)y0 < (unsigned)Hs;
            bool yin1 = (unsigned)(y0 + 1) < (unsigned)Hs;

            float w00 = wp * (1.f - lx) * (1.f - ly) * (float)(xin0 && yin0);
            float w10 = wp * lx * (1.f - ly)         * (float)(xin1 && yin0);
            float w01 = wp * (1.f - lx) * ly         * (float)(xin0 && yin1);
            float w11 = wp * lx * ly                 * (float)(xin1 && yin1);

            int x0c = min(max(x0, 0), Ws - 1);
            int x1c = min(max(x0 + 1, 0), Ws - 1);
            int y0c = min(max(y0, 0), Hs - 1);
            int y1c = min(max(y0 + 1, 0), Hs - 1);

            size_t i00 = (size_t)(st + y0c * Ws + x0c) * 128;
            size_t i10 = (size_t)(st + y0c * Ws + x1c) * 128;
            size_t i01 = (size_t)(st + y1c * Ws + x0c) * 128;
            size_t i11 = (size_t)(st + y1c * Ws + x1c) * 128;

            __half2 v00 = __ldg(vb + i00), v10 = __ldg(vb + i10);
            __half2 v01 = __ldg(vb + i01), v11 = __ldg(vb + i11);
            float2 f00 = __half22float2(v00);
            float2 f10 = __half22float2(v10);
            float2 f01 = __half22float2(v01);
            float2 f11 = __half22float2(v11);

            acc0 = fmaf(w00, f00.x, fmaf(w10, f10.x, fmaf(w01, f01.x, fmaf(w11, f11.x, acc0))));
            acc1 = fmaf(w00, f00.y, fmaf(w10, f10.y, fmaf(w01, f01.y, fmaf(w11, f11.y, acc1))));
        }

        acc0 += __shfl_xor_sync(0xffffffffu, acc0, 16);
        acc1 += __shfl_xor_sync(0xffffffffu, acc1, 16);
        if (hw == 0)
            ((__half2*)out)[(size_t)t * 128 + h * 16 + cl] = __floats2half2_rn(acc0, acc1);
    }
}

// ---------------------------------------------------------------------------
extern "C" void kernel_launch(void* const* d_in, const int* in_sizes, int n_in,
                              void* d_out, int out_size)
{
    const float* src    = (const float*)d_in[0];
    const float* pos    = (const float*)d_in[1];
    const float* refp   = (const float*)d_in[2];
    const float* g1     = (const float*)d_in[5];
    const float* beta1  = (const float*)d_in[6];
    const float* w_off  = (const float*)d_in[7];
    const float* b_off  = (const float*)d_in[8];
    const float* w_attn = (const float*)d_in[9];
    const float* b_attn = (const float*)d_in[10];
    const float* w_val  = (const float*)d_in[11];
    const float* b_val  = (const float*)d_in[12];
    const float* w_out  = (const float*)d_in[13];
    const float* b_out  = (const float*)d_in[14];
    const float* g2     = (const float*)d_in[15];
    const float* beta2  = (const float*)d_in[16];
    const float* w_fc1  = (const float*)d_in[17];
    const float* b_fc1  = (const float*)d_in[18];
    const float* w_fc2  = (const float*)d_in[19];
    const float* b_fc2  = (const float*)d_in[20];
    float* out = (float*)d_out;

    __half *p_xln, *p_q, *p_val, *p_samp, *p_y, *p_h;
    float *p_oa, *p_src2, *p_boa;
    __half *p_wvalT, *p_woaT, *p_woutT, *p_wfc1T, *p_wfc2T;
    cudaGetSymbolAddress((void**)&p_xln,  g_xln_h);
    cudaGetSymbolAddress((void**)&p_q,    g_q_h);
    cudaGetSymbolAddress((void**)&p_val,  g_val_h);
    cudaGetSymbolAddress((void**)&p_samp, g_samp_h);
    cudaGetSymbolAddress((void**)&p_y,    g_y_h);
    cudaGetSymbolAddress((void**)&p_h,    g_h_h);
    cudaGetSymbolAddress((void**)&p_oa,   g_oa);
    cudaGetSymbolAddress((void**)&p_src2, g_src2);
    cudaGetSymbolAddress((void**)&p_boa,  g_boa);
    cudaGetSymbolAddress((void**)&p_wvalT, g_wvalT);
    cudaGetSymbolAddress((void**)&p_woaT,  g_woaT);
    cudaGetSymbolAddress((void**)&p_woutT, g_woutT);
    cudaGetSymbolAddress((void**)&p_wfc1T, g_wfc1T);
    cudaGetSymbolAddress((void**)&p_wfc2T, g_wfc2T);

    cudaFuncSetAttribute(gemm_ln, cudaFuncAttributeMaxDynamicSharedMemorySize, GL_SMEM);

    const int M = TTOK;

    TDescs td;
    td.d[0] = {w_val,  p_wvalT,            256, 256};
    td.d[1] = {w_off,  p_woaT,             256, 256};
    td.d[2] = {w_attn, p_woaT + 256 * 256, 256, 128};
    td.d[3] = {w_out,  p_woutT,            256, 256};
    td.d[4] = {w_fc1,  p_wfc1T,            256, MLPD};
    td.d[5] = {w_fc2,  p_wfc2T,            MLPD, 256};
    transpose_all<<<dim3(32, 32, 6), dim3(32, 8)>>>(td);
    concat_bias<<<1, 384>>>(b_off, b_attn, p_boa);

    // 1) LN1 + q = ln(src) + pos
    ln_kernel<<<TTOK / 8, 256>>>(src, pos, g1, beta1, p_xln, p_q);

    // 2) fused: val = xln @ w_val ; oa = q @ [w_off|w_attn]
    dual_gemm<<<dim3(5, M / 128), 256>>>(p_xln, p_q, p_wvalT, p_woaT,
                                         b_val, p_boa, p_val, p_oa);

    // 3) deformable sampling (fused softmax), grid-stride persistent
    msda_kernel<<<MSDA_BLOCKS, 256>>>(p_val, p_oa, refp, p_samp);

    // 4) src2 = src + samp @ w_out + b_out; y = LN2(src2)   (fused)
    gemm_ln<<<dim3(1, M / 128), 256, GL_SMEM>>>(p_samp, p_woutT, b_out, src,
                                                g2, beta2, p_src2, p_y);

    // 5) h = relu(y @ w_fc1 + b_fc1)
    hgemm<true, false, __half><<<dim3(MLPD / 128, M / 128), 256>>>(p_y, p_wfc1T, b_fc1, nullptr, p_h, M, MLPD, 256);

    // 6) out = src2 + h @ w_fc2 + b_fc2
    hgemm<false, true, float><<<dim3(2, M / 128), 256>>>(p_h, p_wfc2T, b_fc2, p_src2, out, M, 256, 1024);
}

// round 16
// speedup vs baseline: 1.5709x; 1.5709x over previous
#include <cuda_runtime.h>
#include <cuda_fp16.h>
#include <cstdint>

#define BATCH 2
#define LQ    21760
#define TTOK  (BATCH * LQ)     // 43520
#define DMODEL 256
#define NH    8
#define DH    32
#define NL    4
#define NP    4
#define MLPD  1024

__device__ __constant__ int c_H[4]     = {128, 64, 32, 16};
__device__ __constant__ int c_W[4]     = {128, 64, 32, 16};
__device__ __constant__ int c_start[4] = {0, 16384, 20480, 21504};

// fp16 activation scratch
__device__ __half g_xln_h [TTOK * DMODEL];
__device__ __half g_q_h   [TTOK * DMODEL];
__device__ __half g_val_h [TTOK * DMODEL];
__device__ __half g_samp_h[TTOK * DMODEL];
__device__ __half g_y_h   [TTOK * DMODEL];
__device__ __half g_h_h   [TTOK * MLPD];
// fp32 scratch
__device__ float g_oa  [TTOK * 384];
__device__ float g_src2[TTOK * DMODEL];
// transposed fp16 weights [N][K]
__device__ __half g_wvalT [DMODEL * DMODEL];
__device__ __half g_woaT  [384 * DMODEL];
__device__ __half g_woutT [DMODEL * DMODEL];
__device__ __half g_wfc1T [MLPD * DMODEL];
__device__ __half g_wfc2T [DMODEL * MLPD];

// ---------------------------------------------------------------------------
__device__ __forceinline__ void cpasync16(void* smem_dst, const void* gsrc) {
    unsigned dst = (unsigned)__cvta_generic_to_shared(smem_dst);
    asm volatile("cp.async.cg.shared.global [%0], [%1], 16;\n" :: "r"(dst), "l"(gsrc));
}
#define CP_COMMIT() asm volatile("cp.async.commit_group;\n" ::: "memory")
#define CP_WAIT0()  asm volatile("cp.async.wait_group 0;\n" ::: "memory")
#define CP_WAIT1()  asm volatile("cp.async.wait_group 1;\n" ::: "memory")

__device__ __forceinline__ unsigned smem_u32(const void* p) {
    return (unsigned)__cvta_generic_to_shared(p);
}
__device__ __forceinline__ void ldsm_x4(unsigned addr, unsigned& r0, unsigned& r1,
                                        unsigned& r2, unsigned& r3) {
    asm volatile("ldmatrix.sync.aligned.m8n8.x4.shared.b16 {%0,%1,%2,%3}, [%4];\n"
                 : "=r"(r0), "=r"(r1), "=r"(r2), "=r"(r3) : "r"(addr));
}
#define MMA16816(d, a, b0, b1) \
    asm volatile( \
        "mma.sync.aligned.m16n8k16.row.col.f32.f16.f16.f32 " \
        "{%0,%1,%2,%3}, {%4,%5,%6,%7}, {%8,%9}, {%0,%1,%2,%3};\n" \
        : "+f"((d)[0]), "+f"((d)[1]), "+f"((d)[2]), "+f"((d)[3]) \
        : "r"((a)[0]), "r"((a)[1]), "r"((a)[2]), "r"((a)[3]), "r"(b0), "r"(b1))

#define HS_STRIDE 40
#define HS_TILE   (128 * HS_STRIDE)

// ---------------------------------------------------------------------------
// Weight transpose+convert
// ---------------------------------------------------------------------------
struct TDesc { const float* in; __half* out; int K; int N; };
struct TDescs { TDesc d[6]; };

__global__ __launch_bounds__(256) void transpose_all(TDescs td)
{
    TDesc w = td.d[blockIdx.z];
    int n0 = blockIdx.x * 32, k0 = blockIdx.y * 32;
    if (n0 >= w.N || k0 >= w.K) return;
    __shared__ float tile[32][33];
    int tx = threadIdx.x, ty = threadIdx.y;
#pragma unroll
    for (int dy = 0; dy < 32; dy += 8)
        tile[ty + dy][tx] = w.in[(size_t)(k0 + ty + dy) * w.N + n0 + tx];
    __syncthreads();
#pragma unroll
    for (int dy = 0; dy < 32; dy += 8)
        w.out[(size_t)(n0 + ty + dy) * w.K + k0 + tx] = __float2half(tile[tx][ty + dy]);
}

// ---------------------------------------------------------------------------
// LayerNorm (LN1): one warp per token; also writes q = ln + pos.
// ---------------------------------------------------------------------------
__global__ __launch_bounds__(256) void ln_kernel(
    const float* __restrict__ x, const float* __restrict__ pos,
    const float* __restrict__ g, const float* __restrict__ b,
    __half* __restrict__ out, __half* __restrict__ qout)
{
    int warp = threadIdx.x >> 5, lane = threadIdx.x & 31;
    int t = blockIdx.x * 8 + warp;
    if (t >= TTOK) return;

    const float4* xr = (const float4*)(x + (size_t)t * DMODEL);
    float4 v0 = xr[lane * 2 + 0];
    float4 v1 = xr[lane * 2 + 1];
    float vals[8] = {v0.x, v0.y, v0.z, v0.w, v1.x, v1.y, v1.z, v1.w};

    float s = 0.f;
#pragma unroll
    for (int i = 0; i < 8; i++) s += vals[i];
#pragma unroll
    for (int o = 16; o; o >>= 1) s += __shfl_xor_sync(0xffffffffu, s, o);
    float mu = s * (1.0f / 256.0f);

    float vs = 0.f;
#pragma unroll
    for (int i = 0; i < 8; i++) { float d = vals[i] - mu; vs += d * d; }
#pragma unroll
    for (int o = 16; o; o >>= 1) vs += __shfl_xor_sync(0xffffffffu, vs, o);
    float rstd = rsqrtf(vs * (1.0f / 256.0f) + 1e-6f);

    int c0 = lane * 8;
    float o8[8];
#pragma unroll
    for (int i = 0; i < 8; i++) {
        int c = c0 + i;
        o8[i] = (vals[i] - mu) * rstd * g[c] + b[c];
    }
    __half2* orow = (__half2*)(out + (size_t)t * DMODEL);
#pragma unroll
    for (int i = 0; i < 4; i++)
        orow[lane * 4 + i] = __floats2half2_rn(o8[2 * i], o8[2 * i + 1]);

    if (qout) {
        const float4* pr = (const float4*)(pos + (size_t)t * DMODEL);
        float4 p0 = pr[lane * 2 + 0];
        float4 p1 = pr[lane * 2 + 1];
        float p8[8] = {p0.x, p0.y, p0.z, p0.w, p1.x, p1.y, p1.z, p1.w};
        __half2* qrow = (__half2*)(qout + (size_t)t * DMODEL);
#pragma unroll
        for (int i = 0; i < 4; i++)
            qrow[lane * 4 + i] = __floats2half2_rn(o8[2 * i] + p8[2 * i], o8[2 * i + 1] + p8[2 * i + 1]);
    }
}

// ---------------------------------------------------------------------------
// fp32-acc GEMM (BK=32, 2 CTA/SM) — fc1/fc2.
// ---------------------------------------------------------------------------
template<bool RELU, bool RES, typename OutT>
__global__ __launch_bounds__(256, 2) void hgemm(
    const __half* __restrict__ A, const __half* __restrict__ Wt,
    const float* __restrict__ bias, const float* __restrict__ res,
    OutT* __restrict__ C, int M, int N, int K)
{
    __shared__ __half As[2 * HS_TILE];
    __shared__ __half Bs[2 * HS_TILE];

    int tid  = threadIdx.x;
    int lane = tid & 31, warp = tid >> 5;
    int g  = lane >> 2, tg = lane & 3;
    int wm = (warp & 3) * 32;
    int wn = (warp >> 2) * 64;
    int rb = blockIdx.y * 128, cb = blockIdx.x * 128;

    int lr = tid >> 2, lc = tid & 3;
    int a_row = (lane & 15), a_k = (lane >> 4) * 8;
    int b_row = (lane & 7) + ((lane >> 4) << 3), b_k = ((lane >> 3) & 1) * 8;

    float acc[2][8][4];
#pragma unroll
    for (int mi = 0; mi < 2; mi++)
#pragma unroll
        for (int ni = 0; ni < 8; ni++)
#pragma unroll
            for (int v = 0; v < 4; v++) acc[mi][ni][v] = 0.f;

    auto issue = [&](int kt, int buf) {
        int k0 = kt * 32;
#pragma unroll
        for (int i = 0; i < 2; i++) {
            int r = lr + 64 * i;
            cpasync16(As + buf * HS_TILE + r * HS_STRIDE + lc * 8,
                      A + (size_t)(rb + r) * K + k0 + lc * 8);
            cpasync16(Bs + buf * HS_TILE + r * HS_STRIDE + lc * 8,
                      Wt + (size_t)(cb + r) * K + k0 + lc * 8);
        }
    };

    int nt = K >> 5;
    issue(0, 0);
    CP_COMMIT();

    for (int kt = 0; kt < nt; kt++) {
        CP_WAIT0();
        __syncthreads();
        if (kt + 1 < nt) { issue(kt + 1, (kt + 1) & 1); CP_COMMIT(); }

        const __half* Ab = As + (kt & 1) * HS_TILE;
        const __half* Bb = Bs + (kt & 1) * HS_TILE;

#pragma unroll
        for (int ks = 0; ks < 2; ks++) {
            int k0 = ks * 16;
            unsigned a[2][4];
#pragma unroll
            for (int mi = 0; mi < 2; mi++) {
                unsigned addr = smem_u32(Ab + (wm + mi * 16 + a_row) * HS_STRIDE + k0 + a_k);
                ldsm_x4(addr, a[mi][0], a[mi][1], a[mi][2], a[mi][3]);
            }
#pragma unroll
            for (int nj = 0; nj < 4; nj++) {
                unsigned b0, b1, b2, b3;
                unsigned addr = smem_u32(Bb + (wn + nj * 16 + b_row) * HS_STRIDE + k0 + b_k);
                ldsm_x4(addr, b0, b1, b2, b3);
#pragma unroll
                for (int mi = 0; mi < 2; mi++) {
                    MMA16816(acc[mi][2 * nj], a[mi], b0, b1);
                    MMA16816(acc[mi][2 * nj + 1], a[mi], b2, b3);
                }
            }
        }
        __syncthreads();
    }

#pragma unroll
    for (int mi = 0; mi < 2; mi++) {
        int r0 = rb + wm + mi * 16 + g;
#pragma unroll
        for (int ni = 0; ni < 8; ni++) {
            int cc = cb + wn + ni * 8 + 2 * tg;
            float bv0 = bias[cc], bv1 = bias[cc + 1];
            float v0 = acc[mi][ni][0] + bv0;
            float v1 = acc[mi][ni][1] + bv1;
            float v2 = acc[mi][ni][2] + bv0;
            float v3 = acc[mi][ni][3] + bv1;
            size_t o0 = (size_t)r0 * N + cc;
            size_t o1 = (size_t)(r0 + 8) * N + cc;
            if (RES) {
                v0 += res[o0]; v1 += res[o0 + 1];
                v2 += res[o1]; v3 += res[o1 + 1];
            }
            if (RELU) {
                v0 = fmaxf(v0, 0.f); v1 = fmaxf(v1, 0.f);
                v2 = fmaxf(v2, 0.f); v3 = fmaxf(v3, 0.f);
            }
            if (sizeof(OutT) == 2) {
                *(__half2*)((__half*)C + o0) = __floats2half2_rn(v0, v1);
                *(__half2*)((__half*)C + o1) = __floats2half2_rn(v2, v3);
            } else {
                *(float2*)((float*)C + o0) = make_float2(v0, v1);
                *(float2*)((float*)C + o1) = make_float2(v2, v3);
            }
        }
    }
}

// ---------------------------------------------------------------------------
// Fused val+oa GEMM; bias pointer chosen per-tile (no concat needed).
// grid.x<2: val tile (A=xln, fp16 out); 2,3: off tiles; 4: attn tile.
// ---------------------------------------------------------------------------
__global__ __launch_bounds__(256, 2) void dual_gemm(
    const __half* __restrict__ xln, const __half* __restrict__ q,
    const __half* __restrict__ wvalT, const __half* __restrict__ woaT,
    const float* __restrict__ bval, const float* __restrict__ boff,
    const float* __restrict__ battn,
    __half* __restrict__ val_out, float* __restrict__ oa_out)
{
    __shared__ __half As[2 * HS_TILE];
    __shared__ __half Bs[2 * HS_TILE];

    bool isVal = blockIdx.x < 2;
    const __half* A  = isVal ? xln : q;
    const __half* Wt = isVal ? wvalT : woaT;
    int cb = isVal ? (int)blockIdx.x * 128 : ((int)blockIdx.x - 2) * 128;
    // per-tile bias (uniform within the 128-col tile)
    const float* bias = isVal ? (bval + cb)
                              : (cb < 256 ? boff + cb : battn + (cb - 256));
    int N = isVal ? 256 : 384;
    const int K = 256;

    int tid  = threadIdx.x;
    int lane = tid & 31, warp = tid >> 5;
    int g  = lane >> 2, tg = lane & 3;
    int wm = (warp & 3) * 32;
    int wn = (warp >> 2) * 64;
    int rb = blockIdx.y * 128;

    int lr = tid >> 2, lc = tid & 3;
    int a_row = (lane & 15), a_k = (lane >> 4) * 8;
    int b_row = (lane & 7) + ((lane >> 4) << 3), b_k = ((lane >> 3) & 1) * 8;

    float acc[2][8][4];
#pragma unroll
    for (int mi = 0; mi < 2; mi++)
#pragma unroll
        for (int ni = 0; ni < 8; ni++)
#pragma unroll
            for (int v = 0; v < 4; v++) acc[mi][ni][v] = 0.f;

    auto issue = [&](int kt, int buf) {
        int k0 = kt * 32;
#pragma unroll
        for (int i = 0; i < 2; i++) {
            int r = lr + 64 * i;
            cpasync16(As + buf * HS_TILE + r * HS_STRIDE + lc * 8,
                      A + (size_t)(rb + r) * K + k0 + lc * 8);
            cpasync16(Bs + buf * HS_TILE + r * HS_STRIDE + lc * 8,
                      Wt + (size_t)(cb + r) * K + k0 + lc * 8);
        }
    };

    int nt = K >> 5;
    issue(0, 0);
    CP_COMMIT();

    for (int kt = 0; kt < nt; kt++) {
        CP_WAIT0();
        __syncthreads();
        if (kt + 1 < nt) { issue(kt + 1, (kt + 1) & 1); CP_COMMIT(); }

        const __half* Ab = As + (kt & 1) * HS_TILE;
        const __half* Bb = Bs + (kt & 1) * HS_TILE;

#pragma unroll
        for (int ks = 0; ks < 2; ks++) {
            int k0 = ks * 16;
            unsigned a[2][4];
#pragma unroll
            for (int mi = 0; mi < 2; mi++) {
                unsigned addr = smem_u32(Ab + (wm + mi * 16 + a_row) * HS_STRIDE + k0 + a_k);
                ldsm_x4(addr, a[mi][0], a[mi][1], a[mi][2], a[mi][3]);
            }
#pragma unroll
            for (int nj = 0; nj < 4; nj++) {
                unsigned b0, b1, b2, b3;
                unsigned addr = smem_u32(Bb + (wn + nj * 16 + b_row) * HS_STRIDE + k0 + b_k);
                ldsm_x4(addr, b0, b1, b2, b3);
#pragma unroll
                for (int mi = 0; mi < 2; mi++) {
                    MMA16816(acc[mi][2 * nj], a[mi], b0, b1);
                    MMA16816(acc[mi][2 * nj + 1], a[mi], b2, b3);
                }
            }
        }
        __syncthreads();
    }

#pragma unroll
    for (int mi = 0; mi < 2; mi++) {
        int r0 = rb + wm + mi * 16 + g;
#pragma unroll
        for (int ni = 0; ni < 8; ni++) {
            int ccl = wn + ni * 8 + 2 * tg;          // local col in tile
            int cc  = cb + ccl;                       // global col
            float bv0 = bias[ccl], bv1 = bias[ccl + 1];
            float v0 = acc[mi][ni][0] + bv0;
            float v1 = acc[mi][ni][1] + bv1;
            float v2 = acc[mi][ni][2] + bv0;
            float v3 = acc[mi][ni][3] + bv1;
            size_t o0 = (size_t)r0 * N + cc;
            size_t o1 = (size_t)(r0 + 8) * N + cc;
            if (isVal) {
                *(__half2*)(val_out + o0) = __floats2half2_rn(v0, v1);
                *(__half2*)(val_out + o1) = __floats2half2_rn(v2, v3);
            } else {
                *(float2*)(oa_out + o0) = make_float2(v0, v1);
                *(float2*)(oa_out + o1) = make_float2(v2, v3);
            }
        }
    }
}

// ---------------------------------------------------------------------------
// Fused w_out GEMM + residual + LayerNorm2 (round-9 validated, 256 threads).
// ---------------------------------------------------------------------------
#define GL_STRIDE 40
#define GL_A_H    (128 * GL_STRIDE)
#define GL_B_H    (256 * GL_STRIDE)
#define GL_STG_H  (GL_A_H + GL_B_H)
#define GL_SMEM   (3 * GL_STG_H * 2)    // 92160 bytes

__global__ __launch_bounds__(256, 1) void gemm_ln(
    const __half* __restrict__ A, const __half* __restrict__ Wt,
    const float* __restrict__ bias, const float* __restrict__ res,
    const float* __restrict__ g2, const float* __restrict__ b2,
    float* __restrict__ src2, __half* __restrict__ y)
{
    extern __shared__ __half sh[];
    const int N = 256, K = 256;

    int tid  = threadIdx.x;
    int lane = tid & 31, warp = tid >> 5;
    int g  = lane >> 2, tg = lane & 3;
    int wm = (warp & 1) * 64;
    int wn = (warp >> 1) * 64;
    int wnq = warp >> 1;
    int rb = blockIdx.y * 128;

    int a_row = (lane & 15), a_k = (lane >> 4) * 8;
    int b_row = (lane & 7) + ((lane >> 4) << 3), b_k = ((lane >> 3) & 1) * 8;

    float acc[4][8][4];
#pragma unroll
    for (int mi = 0; mi < 4; mi++)
#pragma unroll
        for (int ni = 0; ni < 8; ni++)
#pragma unroll
            for (int v = 0; v < 4; v++) acc[mi][ni][v] = 0.f;

    const __half* Ab = A + (size_t)rb * K;

    auto issue = [&](int kt, int buf) {
        int k0 = kt * 32;
        __half* st = sh + buf * GL_STG_H;
#pragma unroll
        for (int i = 0; i < 6; i++) {
            int chunk = tid + 256 * i;
            if (chunk < 512) {
                int row = chunk >> 2, c16 = chunk & 3;
                cpasync16(st + row * GL_STRIDE + c16 * 8,
                          Ab + (size_t)row * K + k0 + c16 * 8);
            } else {
                int bc = chunk - 512;
                int row = bc >> 2, c16 = bc & 3;
                cpasync16(st + GL_A_H + row * GL_STRIDE + c16 * 8,
                          Wt + (size_t)row * K + k0 + c16 * 8);
            }
        }
    };

    int nt = K >> 5;
    issue(0, 0); CP_COMMIT();
    issue(1, 1); CP_COMMIT();

    for (int kt = 0; kt < nt; kt++) {
        CP_WAIT1();
        __syncthreads();

        int buf = kt % 3;
        const __half* Abs = sh + buf * GL_STG_H;
        const __half* Bbs = Abs + GL_A_H;

#pragma unroll
        for (int ks = 0; ks < 2; ks++) {
            int k0 = ks * 16;
            unsigned a[4][4];
#pragma unroll
            for (int mi = 0; mi < 4; mi++) {
                unsigned addr = smem_u32(Abs + (wm + mi * 16 + a_row) * GL_STRIDE + k0 + a_k);
                ldsm_x4(addr, a[mi][0], a[mi][1], a[mi][2], a[mi][3]);
            }
#pragma unroll
            for (int nj = 0; nj < 4; nj++) {
                unsigned b0, b1, b2, b3;
                unsigned addr = smem_u32(Bbs + (wn + nj * 16 + b_row) * GL_STRIDE + k0 + b_k);
                ldsm_x4(addr, b0, b1, b2, b3);
#pragma unroll
                for (int mi = 0; mi < 4; mi++) {
                    MMA16816(acc[mi][2 * nj], a[mi], b0, b1);
                    MMA16816(acc[mi][2 * nj + 1], a[mi], b2, b3);
                }
            }
        }
        if (kt + 2 < nt) issue(kt + 2, (kt + 2) % 3);
        CP_COMMIT();
    }

    CP_WAIT0();
    __syncthreads();
    float2* part = (float2*)sh;

#pragma unroll
    for (int mi = 0; mi < 4; mi++) {
        int r0 = rb + wm + mi * 16 + g;
        float s0 = 0.f, q0 = 0.f, s1 = 0.f, q1 = 0.f;
#pragma unroll
        for (int ni = 0; ni < 8; ni++) {
            int cc = wn + ni * 8 + 2 * tg;
            float bv0 = bias[cc], bv1 = bias[cc + 1];
            size_t o0 = (size_t)r0 * N + cc;
            size_t o1 = (size_t)(r0 + 8) * N + cc;
            float v0 = acc[mi][ni][0] + bv0 + res[o0];
            float v1 = acc[mi][ni][1] + bv1 + res[o0 + 1];
            float v2 = acc[mi][ni][2] + bv0 + res[o1];
            float v3 = acc[mi][ni][3] + bv1 + res[o1 + 1];
            acc[mi][ni][0] = v0; acc[mi][ni][1] = v1;
            acc[mi][ni][2] = v2; acc[mi][ni][3] = v3;
            *(float2*)(src2 + o0) = make_float2(v0, v1);
            *(float2*)(src2 + o1) = make_float2(v2, v3);
            s0 += v0 + v1; q0 += v0 * v0 + v1 * v1;
            s1 += v2 + v3; q1 += v2 * v2 + v3 * v3;
        }
#pragma unroll
        for (int o = 1; o < 4; o <<= 1) {
            s0 += __shfl_xor_sync(0xffffffffu, s0, o);
            q0 += __shfl_xor_sync(0xffffffffu, q0, o);
            s1 += __shfl_xor_sync(0xffffffffu, s1, o);
            q1 += __shfl_xor_sync(0xffffffffu, q1, o);
        }
        if (tg == 0) {
            int rl = wm + mi * 16 + g;
            part[rl * 4 + wnq]       = make_float2(s0, q0);
            part[(rl + 8) * 4 + wnq] = make_float2(s1, q1);
        }
    }
    __syncthreads();

#pragma unroll
    for (int mi = 0; mi < 4; mi++) {
        int rl = wm + mi * 16 + g;
        float2 pa0 = part[rl * 4 + 0], pa1 = part[rl * 4 + 1],
               pa2 = part[rl * 4 + 2], pa3 = part[rl * 4 + 3];
        float2 pb0 = part[(rl + 8) * 4 + 0], pb1 = part[(rl + 8) * 4 + 1],
               pb2 = part[(rl + 8) * 4 + 2], pb3 = part[(rl + 8) * 4 + 3];
        float sum0 = pa0.x + pa1.x + pa2.x + pa3.x;
        float sq0  = pa0.y + pa1.y + pa2.y + pa3.y;
        float sum1 = pb0.x + pb1.x + pb2.x + pb3.x;
        float sq1  = pb0.y + pb1.y + pb2.y + pb3.y;
        float mu0 = sum0 * (1.f / 256.f);
        float mu1 = sum1 * (1.f / 256.f);
        float rs0 = rsqrtf(fmaxf(sq0 * (1.f / 256.f) - mu0 * mu0, 0.f) + 1e-6f);
        float rs1 = rsqrtf(fmaxf(sq1 * (1.f / 256.f) - mu1 * mu1, 0.f) + 1e-6f);
        int r0 = rb + rl;
#pragma unroll
        for (int ni = 0; ni < 8; ni++) {
            int cc = wn + ni * 8 + 2 * tg;
            float gg0 = g2[cc], gg1 = g2[cc + 1];
            float bb0 = b2[cc], bb1 = b2[cc + 1];
            float y0 = (acc[mi][ni][0] - mu0) * rs0 * gg0 + bb0;
            float y1 = (acc[mi][ni][1] - mu0) * rs0 * gg1 + bb1;
            float y2 = (acc[mi][ni][2] - mu1) * rs1 * gg0 + bb0;
            float y3 = (acc[mi][ni][3] - mu1) * rs1 * gg1 + bb1;
            *(__half2*)(y + (size_t)r0 * N + cc)       = __floats2half2_rn(y0, y1);
            *(__half2*)(y + (size_t)(r0 + 8) * N + cc) = __floats2half2_rn(y2, y3);
        }
    }
}

// ---------------------------------------------------------------------------
// Deformable attention sampling — round-9 validated form, untouched.
// One block per token, one warp per head, half-warp = channel pairs.
// ---------------------------------------------------------------------------
__global__ __launch_bounds__(256) void msda_kernel(
    const __half* __restrict__ val, const float* __restrict__ oa,
    const float* __restrict__ refp, __half* __restrict__ out)
{
    int t = blockIdx.x;
    int h = threadIdx.x >> 5;
    int lane = threadIdx.x & 31;
    int hw = lane >> 4, cl = lane & 15;
    int b = t / LQ;

    const float* oarow = oa + (size_t)t * 384;

    float lg = -1e30f;
    if (lane < 16) lg = oarow[256 + h * 16 + lane];
    float mx = lg;
#pragma unroll
    for (int o = 8; o; o >>= 1) mx = fmaxf(mx, __shfl_xor_sync(0xffffffffu, mx, o));
    float ex = (lane < 16) ? __expf(lg - mx) : 0.f;
    float sm = ex;
#pragma unroll
    for (int o = 8; o; o >>= 1) sm += __shfl_xor_sync(0xffffffffu, sm, o);
    float w = (lane < 16) ? (ex / sm) : 0.f;

    float xf = 0.f, yf = 0.f;
    if (lane < 16) {
        int l = lane >> 2;
        float ox = oarow[h * 32 + lane * 2 + 0];
        float oy = oarow[h * 32 + lane * 2 + 1];
        float Wsf = (float)c_W[l], Hsf = (float)c_H[l];
        float locx = refp[(size_t)t * 8 + l * 2 + 0] + ox / Wsf;
        float locy = refp[(size_t)t * 8 + l * 2 + 1] + oy / Hsf;
        xf = locx * Wsf - 0.5f;
        yf = locy * Hsf - 0.5f;
    }

    float acc0 = 0.f, acc1 = 0.f;
    const __half2* vb = (const __half2*)val + (size_t)b * LQ * 128 + h * 16 + cl;

#pragma unroll
    for (int j = 0; j < 8; j++) {
        int p = 2 * j + hw;
        float xp = __shfl_sync(0xffffffffu, xf, p);
        float yp = __shfl_sync(0xffffffffu, yf, p);
        float wp = __shfl_sync(0xffffffffu, w, p);
        int l = p >> 2;
        int Hs = c_H[l], Ws = c_W[l], st = c_start[l];

        float x0f = floorf(xp), y0f = floorf(yp);
        float lx = xp - x0f, ly = yp - y0f;
        int x0 = (int)x0f, y0 = (int)y0f;

        bool xin0 = (unsigned)x0 < (unsigned)Ws;
        bool xin1 = (unsigned)(x0 + 1) < (unsigned)Ws;
        bool yin0 = (unsigned)y0 < (unsigned)Hs;
        bool yin1 = (unsigned)(y0 + 1) < (unsigned)Hs;

        float w00 = wp * (1.f - lx) * (1.f - ly) * (float)(xin0 && yin0);
        float w10 = wp * lx * (1.f - ly)         * (float)(xin1 && yin0);
        float w01 = wp * (1.f - lx) * ly         * (float)(xin0 && yin1);
        float w11 = wp * lx * ly                 * (float)(xin1 && yin1);

        int x0c = min(max(x0, 0), Ws - 1);
        int x1c = min(max(x0 + 1, 0), Ws - 1);
        int y0c = min(max(y0, 0), Hs - 1);
        int y1c = min(max(y0 + 1, 0), Hs - 1);

        size_t i00 = (size_t)(st + y0c * Ws + x0c) * 128;
        size_t i10 = (size_t)(st + y0c * Ws + x1c) * 128;
        size_t i01 = (size_t)(st + y1c * Ws + x0c) * 128;
        size_t i11 = (size_t)(st + y1c * Ws + x1c) * 128;

        __half2 v00 = __ldg(vb + i00), v10 = __ldg(vb + i10);
        __half2 v01 = __ldg(vb + i01), v11 = __ldg(vb + i11);
        float2 f00 = __half22float2(v00);
        float2 f10 = __half22float2(v10);
        float2 f01 = __half22float2(v01);
        float2 f11 = __half22float2(v11);

        acc0 = fmaf(w00, f00.x, fmaf(w10, f10.x, fmaf(w01, f01.x, fmaf(w11, f11.x, acc0))));
        acc1 = fmaf(w00, f00.y, fmaf(w10, f10.y, fmaf(w01, f01.y, fmaf(w11, f11.y, acc1))));
    }

    acc0 += __shfl_xor_sync(0xffffffffu, acc0, 16);
    acc1 += __shfl_xor_sync(0xffffffffu, acc1, 16);
    if (hw == 0)
        ((__half2*)out)[(size_t)t * 128 + h * 16 + cl] = __floats2half2_rn(acc0, acc1);
}

// ---------------------------------------------------------------------------
extern "C" void kernel_launch(void* const* d_in, const int* in_sizes, int n_in,
                              void* d_out, int out_size)
{
    const float* src    = (const float*)d_in[0];
    const float* pos    = (const float*)d_in[1];
    const float* refp   = (const float*)d_in[2];
    const float* g1     = (const float*)d_in[5];
    const float* beta1  = (const float*)d_in[6];
    const float* w_off  = (const float*)d_in[7];
    const float* b_off  = (const float*)d_in[8];
    const float* w_attn = (const float*)d_in[9];
    const float* b_attn = (const float*)d_in[10];
    const float* w_val  = (const float*)d_in[11];
    const float* b_val  = (const float*)d_in[12];
    const float* w_out  = (const float*)d_in[13];
    const float* b_out  = (const float*)d_in[14];
    const float* g2     = (const float*)d_in[15];
    const float* beta2  = (const float*)d_in[16];
    const float* w_fc1  = (const float*)d_in[17];
    const float* b_fc1  = (const float*)d_in[18];
    const float* w_fc2  = (const float*)d_in[19];
    const float* b_fc2  = (const float*)d_in[20];
    float* out = (float*)d_out;

    __half *p_xln, *p_q, *p_val, *p_samp, *p_y, *p_h;
    float *p_oa, *p_src2;
    __half *p_wvalT, *p_woaT, *p_woutT, *p_wfc1T, *p_wfc2T;
    cudaGetSymbolAddress((void**)&p_xln,  g_xln_h);
    cudaGetSymbolAddress((void**)&p_q,    g_q_h);
    cudaGetSymbolAddress((void**)&p_val,  g_val_h);
    cudaGetSymbolAddress((void**)&p_samp, g_samp_h);
    cudaGetSymbolAddress((void**)&p_y,    g_y_h);
    cudaGetSymbolAddress((void**)&p_h,    g_h_h);
    cudaGetSymbolAddress((void**)&p_oa,   g_oa);
    cudaGetSymbolAddress((void**)&p_src2, g_src2);
    cudaGetSymbolAddress((void**)&p_wvalT, g_wvalT);
    cudaGetSymbolAddress((void**)&p_woaT,  g_woaT);
    cudaGetSymbolAddress((void**)&p_woutT, g_woutT);
    cudaGetSymbolAddress((void**)&p_wfc1T, g_wfc1T);
    cudaGetSymbolAddress((void**)&p_wfc2T, g_wfc2T);

    cudaFuncSetAttribute(gemm_ln, cudaFuncAttributeMaxDynamicSharedMemorySize, GL_SMEM);

    const int M = TTOK;

    // 0) weight transposes (one launch)
    TDescs td;
    td.d[0] = {w_val,  p_wvalT,            256, 256};
    td.d[1] = {w_off,  p_woaT,             256, 256};
    td.d[2] = {w_attn, p_woaT + 256 * 256, 256, 128};
    td.d[3] = {w_out,  p_woutT,            256, 256};
    td.d[4] = {w_fc1,  p_wfc1T,            256, MLPD};
    td.d[5] = {w_fc2,  p_wfc2T,            MLPD, 256};
    transpose_all<<<dim3(32, 32, 6), dim3(32, 8)>>>(td);

    // 1) LN1 + q = ln(src) + pos
    ln_kernel<<<TTOK / 8, 256>>>(src, pos, g1, beta1, p_xln, p_q);

    // 2) fused: val = xln @ w_val ; oa = q @ [w_off|w_attn]  (per-tile bias)
    dual_gemm<<<dim3(5, M / 128), 256>>>(p_xln, p_q, p_wvalT, p_woaT,
                                         b_val, b_off, b_attn, p_val, p_oa);

    // 3) deformable sampling (fused softmax) — round-9 form
    msda_kernel<<<TTOK, 256>>>(p_val, p_oa, refp, p_samp);

    // 4) src2 = src + samp @ w_out + b_out; y = LN2(src2)   (fused)
    gemm_ln<<<dim3(1, M / 128), 256, GL_SMEM>>>(p_samp, p_woutT, b_out, src,
                                                g2, beta2, p_src2, p_y);

    // 5) h = relu(y @ w_fc1 + b_fc1)
    hgemm<true, false, __half><<<dim3(MLPD / 128, M / 128), 256>>>(p_y, p_wfc1T, b_fc1, nullptr, p_h, M, MLPD, 256);

    // 6) out = src2 + h @ w_fc2 + b_fc2
    hgemm<false, true, float><<<dim3(2, M / 128), 256>>>(p_h, p_wfc2T, b_fc2, p_src2, out, M, 256, 1024);
}

// round 17
// speedup vs baseline: 1.8782x; 1.1957x over previous
#include <cuda_runtime.h>
#include <cuda_fp16.h>
#include <cstdint>

#define BATCH 2
#define LQ    21760
#define TTOK  (BATCH * LQ)     // 43520
#define DMODEL 256
#define NH    8
#define DH    32
#define NL    4
#define NP    4
#define MLPD  1024

__device__ __constant__ int c_H[4]     = {128, 64, 32, 16};
__device__ __constant__ int c_W[4]     = {128, 64, 32, 16};
__device__ __constant__ int c_start[4] = {0, 16384, 20480, 21504};

// fp16 activation scratch
__device__ __half g_xln_h [TTOK * DMODEL];
__device__ __half g_q_h   [TTOK * DMODEL];
__device__ __half g_val_h [TTOK * DMODEL];
__device__ __half g_samp_h[TTOK * DMODEL];
__device__ __half g_y_h   [TTOK * DMODEL];
__device__ __half g_h_h   [TTOK * MLPD];
// fp32 scratch
__device__ float g_oa  [TTOK * 384];
__device__ float g_src2[TTOK * DMODEL];
// transposed fp16 weights [N][K]
__device__ __half g_wvalT [DMODEL * DMODEL];
__device__ __half g_woaT  [384 * DMODEL];
__device__ __half g_woutT [DMODEL * DMODEL];
__device__ __half g_wfc1T [MLPD * DMODEL];
__device__ __half g_wfc2T [DMODEL * MLPD];

// ---------------------------------------------------------------------------
__device__ __forceinline__ void cpasync16(void* smem_dst, const void* gsrc) {
    unsigned dst = (unsigned)__cvta_generic_to_shared(smem_dst);
    asm volatile("cp.async.cg.shared.global [%0], [%1], 16;\n" :: "r"(dst), "l"(gsrc));
}
#define CP_COMMIT() asm volatile("cp.async.commit_group;\n" ::: "memory")
#define CP_WAIT0()  asm volatile("cp.async.wait_group 0;\n" ::: "memory")
#define CP_WAIT1()  asm volatile("cp.async.wait_group 1;\n" ::: "memory")

__device__ __forceinline__ unsigned smem_u32(const void* p) {
    return (unsigned)__cvta_generic_to_shared(p);
}
__device__ __forceinline__ void ldsm_x4(unsigned addr, unsigned& r0, unsigned& r1,
                                        unsigned& r2, unsigned& r3) {
    asm volatile("ldmatrix.sync.aligned.m8n8.x4.shared.b16 {%0,%1,%2,%3}, [%4];\n"
                 : "=r"(r0), "=r"(r1), "=r"(r2), "=r"(r3) : "r"(addr));
}
#define MMA16816(d, a, b0, b1) \
    asm volatile( \
        "mma.sync.aligned.m16n8k16.row.col.f32.f16.f16.f32 " \
        "{%0,%1,%2,%3}, {%4,%5,%6,%7}, {%8,%9}, {%0,%1,%2,%3};\n" \
        : "+f"((d)[0]), "+f"((d)[1]), "+f"((d)[2]), "+f"((d)[3]) \
        : "r"((a)[0]), "r"((a)[1]), "r"((a)[2]), "r"((a)[3]), "r"(b0), "r"(b1))

#define HS_STRIDE 40
#define HS_TILE   (128 * HS_STRIDE)

// ---------------------------------------------------------------------------
// Weight transpose+convert
// ---------------------------------------------------------------------------
struct TDesc { const float* in; __half* out; int K; int N; };
struct TDescs { TDesc d[6]; };

__global__ __launch_bounds__(256) void transpose_all(TDescs td)
{
    TDesc w = td.d[blockIdx.z];
    int n0 = blockIdx.x * 32, k0 = blockIdx.y * 32;
    if (n0 >= w.N || k0 >= w.K) return;
    __shared__ float tile[32][33];
    int tx = threadIdx.x, ty = threadIdx.y;
#pragma unroll
    for (int dy = 0; dy < 32; dy += 8)
        tile[ty + dy][tx] = w.in[(size_t)(k0 + ty + dy) * w.N + n0 + tx];
    __syncthreads();
#pragma unroll
    for (int dy = 0; dy < 32; dy += 8)
        w.out[(size_t)(n0 + ty + dy) * w.K + k0 + tx] = __float2half(tile[tx][ty + dy]);
}

// ---------------------------------------------------------------------------
// LayerNorm (LN1): one warp per token; also writes q = ln + pos.
// ---------------------------------------------------------------------------
__global__ __launch_bounds__(256) void ln_kernel(
    const float* __restrict__ x, const float* __restrict__ pos,
    const float* __restrict__ g, const float* __restrict__ b,
    __half* __restrict__ out, __half* __restrict__ qout)
{
    int warp = threadIdx.x >> 5, lane = threadIdx.x & 31;
    int t = blockIdx.x * 8 + warp;
    if (t >= TTOK) return;

    const float4* xr = (const float4*)(x + (size_t)t * DMODEL);
    float4 v0 = xr[lane * 2 + 0];
    float4 v1 = xr[lane * 2 + 1];
    float vals[8] = {v0.x, v0.y, v0.z, v0.w, v1.x, v1.y, v1.z, v1.w};

    float s = 0.f;
#pragma unroll
    for (int i = 0; i < 8; i++) s += vals[i];
#pragma unroll
    for (int o = 16; o; o >>= 1) s += __shfl_xor_sync(0xffffffffu, s, o);
    float mu = s * (1.0f / 256.0f);

    float vs = 0.f;
#pragma unroll
    for (int i = 0; i < 8; i++) { float d = vals[i] - mu; vs += d * d; }
#pragma unroll
    for (int o = 16; o; o >>= 1) vs += __shfl_xor_sync(0xffffffffu, vs, o);
    float rstd = rsqrtf(vs * (1.0f / 256.0f) + 1e-6f);

    int c0 = lane * 8;
    float o8[8];
#pragma unroll
    for (int i = 0; i < 8; i++) {
        int c = c0 + i;
        o8[i] = (vals[i] - mu) * rstd * g[c] + b[c];
    }
    __half2* orow = (__half2*)(out + (size_t)t * DMODEL);
#pragma unroll
    for (int i = 0; i < 4; i++)
        orow[lane * 4 + i] = __floats2half2_rn(o8[2 * i], o8[2 * i + 1]);

    if (qout) {
        const float4* pr = (const float4*)(pos + (size_t)t * DMODEL);
        float4 p0 = pr[lane * 2 + 0];
        float4 p1 = pr[lane * 2 + 1];
        float p8[8] = {p0.x, p0.y, p0.z, p0.w, p1.x, p1.y, p1.z, p1.w};
        __half2* qrow = (__half2*)(qout + (size_t)t * DMODEL);
#pragma unroll
        for (int i = 0; i < 4; i++)
            qrow[lane * 4 + i] = __floats2half2_rn(o8[2 * i] + p8[2 * i], o8[2 * i + 1] + p8[2 * i + 1]);
    }
}

// ---------------------------------------------------------------------------
// fp32-acc GEMM (BK=32, 2 CTA/SM) — fc1/fc2.
// ---------------------------------------------------------------------------
template<bool RELU, bool RES, typename OutT>
__global__ __launch_bounds__(256, 2) void hgemm(
    const __half* __restrict__ A, const __half* __restrict__ Wt,
    const float* __restrict__ bias, const float* __restrict__ res,
    OutT* __restrict__ C, int M, int N, int K)
{
    __shared__ __half As[2 * HS_TILE];
    __shared__ __half Bs[2 * HS_TILE];

    int tid  = threadIdx.x;
    int lane = tid & 31, warp = tid >> 5;
    int g  = lane >> 2, tg = lane & 3;
    int wm = (warp & 3) * 32;
    int wn = (warp >> 2) * 64;
    int rb = blockIdx.y * 128, cb = blockIdx.x * 128;

    int lr = tid >> 2, lc = tid & 3;
    int a_row = (lane & 15), a_k = (lane >> 4) * 8;
    int b_row = (lane & 7) + ((lane >> 4) << 3), b_k = ((lane >> 3) & 1) * 8;

    float acc[2][8][4];
#pragma unroll
    for (int mi = 0; mi < 2; mi++)
#pragma unroll
        for (int ni = 0; ni < 8; ni++)
#pragma unroll
            for (int v = 0; v < 4; v++) acc[mi][ni][v] = 0.f;

    auto issue = [&](int kt, int buf) {
        int k0 = kt * 32;
#pragma unroll
        for (int i = 0; i < 2; i++) {
            int r = lr + 64 * i;
            cpasync16(As + buf * HS_TILE + r * HS_STRIDE + lc * 8,
                      A + (size_t)(rb + r) * K + k0 + lc * 8);
            cpasync16(Bs + buf * HS_TILE + r * HS_STRIDE + lc * 8,
                      Wt + (size_t)(cb + r) * K + k0 + lc * 8);
        }
    };

    int nt = K >> 5;
    issue(0, 0);
    CP_COMMIT();

    for (int kt = 0; kt < nt; kt++) {
        CP_WAIT0();
        __syncthreads();
        if (kt + 1 < nt) { issue(kt + 1, (kt + 1) & 1); CP_COMMIT(); }

        const __half* Ab = As + (kt & 1) * HS_TILE;
        const __half* Bb = Bs + (kt & 1) * HS_TILE;

#pragma unroll
        for (int ks = 0; ks < 2; ks++) {
            int k0 = ks * 16;
            unsigned a[2][4];
#pragma unroll
            for (int mi = 0; mi < 2; mi++) {
                unsigned addr = smem_u32(Ab + (wm + mi * 16 + a_row) * HS_STRIDE + k0 + a_k);
                ldsm_x4(addr, a[mi][0], a[mi][1], a[mi][2], a[mi][3]);
            }
#pragma unroll
            for (int nj = 0; nj < 4; nj++) {
                unsigned b0, b1, b2, b3;
                unsigned addr = smem_u32(Bb + (wn + nj * 16 + b_row) * HS_STRIDE + k0 + b_k);
                ldsm_x4(addr, b0, b1, b2, b3);
#pragma unroll
                for (int mi = 0; mi < 2; mi++) {
                    MMA16816(acc[mi][2 * nj], a[mi], b0, b1);
                    MMA16816(acc[mi][2 * nj + 1], a[mi], b2, b3);
                }
            }
        }
        __syncthreads();
    }

#pragma unroll
    for (int mi = 0; mi < 2; mi++) {
        int r0 = rb + wm + mi * 16 + g;
#pragma unroll
        for (int ni = 0; ni < 8; ni++) {
            int cc = cb + wn + ni * 8 + 2 * tg;
            float bv0 = bias[cc], bv1 = bias[cc + 1];
            float v0 = acc[mi][ni][0] + bv0;
            float v1 = acc[mi][ni][1] + bv1;
            float v2 = acc[mi][ni][2] + bv0;
            float v3 = acc[mi][ni][3] + bv1;
            size_t o0 = (size_t)r0 * N + cc;
            size_t o1 = (size_t)(r0 + 8) * N + cc;
            if (RES) {
                v0 += res[o0]; v1 += res[o0 + 1];
                v2 += res[o1]; v3 += res[o1 + 1];
            }
            if (RELU) {
                v0 = fmaxf(v0, 0.f); v1 = fmaxf(v1, 0.f);
                v2 = fmaxf(v2, 0.f); v3 = fmaxf(v3, 0.f);
            }
            if (sizeof(OutT) == 2) {
                *(__half2*)((__half*)C + o0) = __floats2half2_rn(v0, v1);
                *(__half2*)((__half*)C + o1) = __floats2half2_rn(v2, v3);
            } else {
                *(float2*)((float*)C + o0) = make_float2(v0, v1);
                *(float2*)((float*)C + o1) = make_float2(v2, v3);
            }
        }
    }
}

// ---------------------------------------------------------------------------
// Fused val+oa GEMM; bias pointer chosen per-tile.
// ---------------------------------------------------------------------------
__global__ __launch_bounds__(256, 2) void dual_gemm(
    const __half* __restrict__ xln, const __half* __restrict__ q,
    const __half* __restrict__ wvalT, const __half* __restrict__ woaT,
    const float* __restrict__ bval, const float* __restrict__ boff,
    const float* __restrict__ battn,
    __half* __restrict__ val_out, float* __restrict__ oa_out)
{
    __shared__ __half As[2 * HS_TILE];
    __shared__ __half Bs[2 * HS_TILE];

    bool isVal = blockIdx.x < 2;
    const __half* A  = isVal ? xln : q;
    const __half* Wt = isVal ? wvalT : woaT;
    int cb = isVal ? (int)blockIdx.x * 128 : ((int)blockIdx.x - 2) * 128;
    const float* bias = isVal ? (bval + cb)
                              : (cb < 256 ? boff + cb : battn + (cb - 256));
    int N = isVal ? 256 : 384;
    const int K = 256;

    int tid  = threadIdx.x;
    int lane = tid & 31, warp = tid >> 5;
    int g  = lane >> 2, tg = lane & 3;
    int wm = (warp & 3) * 32;
    int wn = (warp >> 2) * 64;
    int rb = blockIdx.y * 128;

    int lr = tid >> 2, lc = tid & 3;
    int a_row = (lane & 15), a_k = (lane >> 4) * 8;
    int b_row = (lane & 7) + ((lane >> 4) << 3), b_k = ((lane >> 3) & 1) * 8;

    float acc[2][8][4];
#pragma unroll
    for (int mi = 0; mi < 2; mi++)
#pragma unroll
        for (int ni = 0; ni < 8; ni++)
#pragma unroll
            for (int v = 0; v < 4; v++) acc[mi][ni][v] = 0.f;

    auto issue = [&](int kt, int buf) {
        int k0 = kt * 32;
#pragma unroll
        for (int i = 0; i < 2; i++) {
            int r = lr + 64 * i;
            cpasync16(As + buf * HS_TILE + r * HS_STRIDE + lc * 8,
                      A + (size_t)(rb + r) * K + k0 + lc * 8);
            cpasync16(Bs + buf * HS_TILE + r * HS_STRIDE + lc * 8,
                      Wt + (size_t)(cb + r) * K + k0 + lc * 8);
        }
    };

    int nt = K >> 5;
    issue(0, 0);
    CP_COMMIT();

    for (int kt = 0; kt < nt; kt++) {
        CP_WAIT0();
        __syncthreads();
        if (kt + 1 < nt) { issue(kt + 1, (kt + 1) & 1); CP_COMMIT(); }

        const __half* Ab = As + (kt & 1) * HS_TILE;
        const __half* Bb = Bs + (kt & 1) * HS_TILE;

#pragma unroll
        for (int ks = 0; ks < 2; ks++) {
            int k0 = ks * 16;
            unsigned a[2][4];
#pragma unroll
            for (int mi = 0; mi < 2; mi++) {
                unsigned addr = smem_u32(Ab + (wm + mi * 16 + a_row) * HS_STRIDE + k0 + a_k);
                ldsm_x4(addr, a[mi][0], a[mi][1], a[mi][2], a[mi][3]);
            }
#pragma unroll
            for (int nj = 0; nj < 4; nj++) {
                unsigned b0, b1, b2, b3;
                unsigned addr = smem_u32(Bb + (wn + nj * 16 + b_row) * HS_STRIDE + k0 + b_k);
                ldsm_x4(addr, b0, b1, b2, b3);
#pragma unroll
                for (int mi = 0; mi < 2; mi++) {
                    MMA16816(acc[mi][2 * nj], a[mi], b0, b1);
                    MMA16816(acc[mi][2 * nj + 1], a[mi], b2, b3);
                }
            }
        }
        __syncthreads();
    }

#pragma unroll
    for (int mi = 0; mi < 2; mi++) {
        int r0 = rb + wm + mi * 16 + g;
#pragma unroll
        for (int ni = 0; ni < 8; ni++) {
            int ccl = wn + ni * 8 + 2 * tg;
            int cc  = cb + ccl;
            float bv0 = bias[ccl], bv1 = bias[ccl + 1];
            float v0 = acc[mi][ni][0] + bv0;
            float v1 = acc[mi][ni][1] + bv1;
            float v2 = acc[mi][ni][2] + bv0;
            float v3 = acc[mi][ni][3] + bv1;
            size_t o0 = (size_t)r0 * N + cc;
            size_t o1 = (size_t)(r0 + 8) * N + cc;
            if (isVal) {
                *(__half2*)(val_out + o0) = __floats2half2_rn(v0, v1);
                *(__half2*)(val_out + o1) = __floats2half2_rn(v2, v3);
            } else {
                *(float2*)(oa_out + o0) = make_float2(v0, v1);
                *(float2*)(oa_out + o1) = make_float2(v2, v3);
            }
        }
    }
}

// ---------------------------------------------------------------------------
// Fused w_out GEMM + residual + LayerNorm2 (validated, 256 threads).
// ---------------------------------------------------------------------------
#define GL_STRIDE 40
#define GL_A_H    (128 * GL_STRIDE)
#define GL_B_H    (256 * GL_STRIDE)
#define GL_STG_H  (GL_A_H + GL_B_H)
#define GL_SMEM   (3 * GL_STG_H * 2)    // 92160 bytes

__global__ __launch_bounds__(256, 1) void gemm_ln(
    const __half* __restrict__ A, const __half* __restrict__ Wt,
    const float* __restrict__ bias, const float* __restrict__ res,
    const float* __restrict__ g2, const float* __restrict__ b2,
    float* __restrict__ src2, __half* __restrict__ y)
{
    extern __shared__ __half sh[];
    const int N = 256, K = 256;

    int tid  = threadIdx.x;
    int lane = tid & 31, warp = tid >> 5;
    int g  = lane >> 2, tg = lane & 3;
    int wm = (warp & 1) * 64;
    int wn = (warp >> 1) * 64;
    int wnq = warp >> 1;
    int rb = blockIdx.y * 128;

    int a_row = (lane & 15), a_k = (lane >> 4) * 8;
    int b_row = (lane & 7) + ((lane >> 4) << 3), b_k = ((lane >> 3) & 1) * 8;

    float acc[4][8][4];
#pragma unroll
    for (int mi = 0; mi < 4; mi++)
#pragma unroll
        for (int ni = 0; ni < 8; ni++)
#pragma unroll
            for (int v = 0; v < 4; v++) acc[mi][ni][v] = 0.f;

    const __half* Ab = A + (size_t)rb * K;

    auto issue = [&](int kt, int buf) {
        int k0 = kt * 32;
        __half* st = sh + buf * GL_STG_H;
#pragma unroll
        for (int i = 0; i < 6; i++) {
            int chunk = tid + 256 * i;
            if (chunk < 512) {
                int row = chunk >> 2, c16 = chunk & 3;
                cpasync16(st + row * GL_STRIDE + c16 * 8,
                          Ab + (size_t)row * K + k0 + c16 * 8);
            } else {
                int bc = chunk - 512;
                int row = bc >> 2, c16 = bc & 3;
                cpasync16(st + GL_A_H + row * GL_STRIDE + c16 * 8,
                          Wt + (size_t)row * K + k0 + c16 * 8);
            }
        }
    };

    int nt = K >> 5;
    issue(0, 0); CP_COMMIT();
    issue(1, 1); CP_COMMIT();

    for (int kt = 0; kt < nt; kt++) {
        CP_WAIT1();
        __syncthreads();

        int buf = kt % 3;
        const __half* Abs = sh + buf * GL_STG_H;
        const __half* Bbs = Abs + GL_A_H;

#pragma unroll
        for (int ks = 0; ks < 2; ks++) {
            int k0 = ks * 16;
            unsigned a[4][4];
#pragma unroll
            for (int mi = 0; mi < 4; mi++) {
                unsigned addr = smem_u32(Abs + (wm + mi * 16 + a_row) * GL_STRIDE + k0 + a_k);
                ldsm_x4(addr, a[mi][0], a[mi][1], a[mi][2], a[mi][3]);
            }
#pragma unroll
            for (int nj = 0; nj < 4; nj++) {
                unsigned b0, b1, b2, b3;
                unsigned addr = smem_u32(Bbs + (wn + nj * 16 + b_row) * GL_STRIDE + k0 + b_k);
                ldsm_x4(addr, b0, b1, b2, b3);
#pragma unroll
                for (int mi = 0; mi < 4; mi++) {
                    MMA16816(acc[mi][2 * nj], a[mi], b0, b1);
                    MMA16816(acc[mi][2 * nj + 1], a[mi], b2, b3);
                }
            }
        }
        if (kt + 2 < nt) issue(kt + 2, (kt + 2) % 3);
        CP_COMMIT();
    }

    CP_WAIT0();
    __syncthreads();
    float2* part = (float2*)sh;

#pragma unroll
    for (int mi = 0; mi < 4; mi++) {
        int r0 = rb + wm + mi * 16 + g;
        float s0 = 0.f, q0 = 0.f, s1 = 0.f, q1 = 0.f;
#pragma unroll
        for (int ni = 0; ni < 8; ni++) {
            int cc = wn + ni * 8 + 2 * tg;
            float bv0 = bias[cc], bv1 = bias[cc + 1];
            size_t o0 = (size_t)r0 * N + cc;
            size_t o1 = (size_t)(r0 + 8) * N + cc;
            float v0 = acc[mi][ni][0] + bv0 + res[o0];
            float v1 = acc[mi][ni][1] + bv1 + res[o0 + 1];
            float v2 = acc[mi][ni][2] + bv0 + res[o1];
            float v3 = acc[mi][ni][3] + bv1 + res[o1 + 1];
            acc[mi][ni][0] = v0; acc[mi][ni][1] = v1;
            acc[mi][ni][2] = v2; acc[mi][ni][3] = v3;
            *(float2*)(src2 + o0) = make_float2(v0, v1);
            *(float2*)(src2 + o1) = make_float2(v2, v3);
            s0 += v0 + v1; q0 += v0 * v0 + v1 * v1;
            s1 += v2 + v3; q1 += v2 * v2 + v3 * v3;
        }
#pragma unroll
        for (int o = 1; o < 4; o <<= 1) {
            s0 += __shfl_xor_sync(0xffffffffu, s0, o);
            q0 += __shfl_xor_sync(0xffffffffu, q0, o);
            s1 += __shfl_xor_sync(0xffffffffu, s1, o);
            q1 += __shfl_xor_sync(0xffffffffu, q1, o);
        }
        if (tg == 0) {
            int rl = wm + mi * 16 + g;
            part[rl * 4 + wnq]       = make_float2(s0, q0);
            part[(rl + 8) * 4 + wnq] = make_float2(s1, q1);
        }
    }
    __syncthreads();

#pragma unroll
    for (int mi = 0; mi < 4; mi++) {
        int rl = wm + mi * 16 + g;
        float2 pa0 = part[rl * 4 + 0], pa1 = part[rl * 4 + 1],
               pa2 = part[rl * 4 + 2], pa3 = part[rl * 4 + 3];
        float2 pb0 = part[(rl + 8) * 4 + 0], pb1 = part[(rl + 8) * 4 + 1],
               pb2 = part[(rl + 8) * 4 + 2], pb3 = part[(rl + 8) * 4 + 3];
        float sum0 = pa0.x + pa1.x + pa2.x + pa3.x;
        float sq0  = pa0.y + pa1.y + pa2.y + pa3.y;
        float sum1 = pb0.x + pb1.x + pb2.x + pb3.x;
        float sq1  = pb0.y + pb1.y + pb2.y + pb3.y;
        float mu0 = sum0 * (1.f / 256.f);
        float mu1 = sum1 * (1.f / 256.f);
        float rs0 = rsqrtf(fmaxf(sq0 * (1.f / 256.f) - mu0 * mu0, 0.f) + 1e-6f);
        float rs1 = rsqrtf(fmaxf(sq1 * (1.f / 256.f) - mu1 * mu1, 0.f) + 1e-6f);
        int r0 = rb + rl;
#pragma unroll
        for (int ni = 0; ni < 8; ni++) {
            int cc = wn + ni * 8 + 2 * tg;
            float gg0 = g2[cc], gg1 = g2[cc + 1];
            float bb0 = b2[cc], bb1 = b2[cc + 1];
            float y0 = (acc[mi][ni][0] - mu0) * rs0 * gg0 + bb0;
            float y1 = (acc[mi][ni][1] - mu0) * rs0 * gg1 + bb1;
            float y2 = (acc[mi][ni][2] - mu1) * rs1 * gg0 + bb0;
            float y3 = (acc[mi][ni][3] - mu1) * rs1 * gg1 + bb1;
            *(__half2*)(y + (size_t)r0 * N + cc)       = __floats2half2_rn(y0, y1);
            *(__half2*)(y + (size_t)(r0 + 8) * N + cc) = __floats2half2_rn(y2, y3);
        }
    }
}

// ---------------------------------------------------------------------------
// Deformable attention sampling v5: issue-optimized.
// Lanes 0-15 precompute their point's 4 clamped indices + 4 weights ONCE
// (parallel across lanes); the gather loop only shuffles them in.
// Same block shape / occupancy / access pattern as the validated form.
// ---------------------------------------------------------------------------
__global__ __launch_bounds__(256) void msda_kernel(
    const __half* __restrict__ val, const float* __restrict__ oa,
    const float* __restrict__ refp, __half* __restrict__ out)
{
    int t = blockIdx.x;
    int h = threadIdx.x >> 5;
    int lane = threadIdx.x & 31;
    int hw = lane >> 4, cl = lane & 15;
    int b = t / LQ;

    const float* oarow = oa + (size_t)t * 384;

    // softmax over 16 weights (lanes 0..15 own one point)
    float lg = -1e30f;
    if (lane < 16) lg = oarow[256 + h * 16 + lane];
    float mx = lg;
#pragma unroll
    for (int o = 8; o; o >>= 1) mx = fmaxf(mx, __shfl_xor_sync(0xffffffffu, mx, o));
    float ex = (lane < 16) ? __expf(lg - mx) : 0.f;
    float sm = ex;
#pragma unroll
    for (int o = 8; o; o >>= 1) sm += __shfl_xor_sync(0xffffffffu, sm, o);
    float w = (lane < 16) ? (ex / sm) : 0.f;

    // per-point FULL precompute in lanes 0..15 (one pass, parallel over lanes)
    int   i00 = 0, i10 = 0, i01 = 0, i11 = 0;
    float w00 = 0.f, w10 = 0.f, w01 = 0.f, w11 = 0.f;
    if (lane < 16) {
        int l = lane >> 2;
        int Hs = c_H[l], Ws = c_W[l], st = c_start[l];
        float ox = oarow[h * 32 + lane * 2 + 0];
        float oy = oarow[h * 32 + lane * 2 + 1];
        float Wsf = (float)Ws, Hsf = (float)Hs;
        float locx = refp[(size_t)t * 8 + l * 2 + 0] + ox / Wsf;
        float locy = refp[(size_t)t * 8 + l * 2 + 1] + oy / Hsf;
        float xf = locx * Wsf - 0.5f;
        float yf = locy * Hsf - 0.5f;

        float x0f = floorf(xf), y0f = floorf(yf);
        float lx = xf - x0f, ly = yf - y0f;
        int x0 = (int)x0f, y0 = (int)y0f;

        bool xin0 = (unsigned)x0 < (unsigned)Ws;
        bool xin1 = (unsigned)(x0 + 1) < (unsigned)Ws;
        bool yin0 = (unsigned)y0 < (unsigned)Hs;
        bool yin1 = (unsigned)(y0 + 1) < (unsigned)Hs;

        w00 = w * (1.f - lx) * (1.f - ly) * (float)(xin0 && yin0);
        w10 = w * lx * (1.f - ly)         * (float)(xin1 && yin0);
        w01 = w * (1.f - lx) * ly         * (float)(xin0 && yin1);
        w11 = w * lx * ly                 * (float)(xin1 && yin1);

        int x0c = min(max(x0, 0), Ws - 1);
        int x1c = min(max(x0 + 1, 0), Ws - 1);
        int y0c = min(max(y0, 0), Hs - 1);
        int y1c = min(max(y0 + 1, 0), Hs - 1);

        i00 = (st + y0c * Ws + x0c) * 128;
        i10 = (st + y0c * Ws + x1c) * 128;
        i01 = (st + y1c * Ws + x0c) * 128;
        i11 = (st + y1c * Ws + x1c) * 128;
    }

    float acc0 = 0.f, acc1 = 0.f;
    const __half2* vb = (const __half2*)val + (size_t)b * LQ * 128 + h * 16 + cl;

#pragma unroll
    for (int j = 0; j < 8; j++) {
        int p = 2 * j + hw;
        int   j00 = __shfl_sync(0xffffffffu, i00, p);
        int   j10 = __shfl_sync(0xffffffffu, i10, p);
        int   j01 = __shfl_sync(0xffffffffu, i01, p);
        int   j11 = __shfl_sync(0xffffffffu, i11, p);
        float u00 = __shfl_sync(0xffffffffu, w00, p);
        float u10 = __shfl_sync(0xffffffffu, w10, p);
        float u01 = __shfl_sync(0xffffffffu, w01, p);
        float u11 = __shfl_sync(0xffffffffu, w11, p);

        __half2 v00 = __ldg(vb + j00), v10 = __ldg(vb + j10);
        __half2 v01 = __ldg(vb + j01), v11 = __ldg(vb + j11);
        float2 f00 = __half22float2(v00);
        float2 f10 = __half22float2(v10);
        float2 f01 = __half22float2(v01);
        float2 f11 = __half22float2(v11);

        acc0 = fmaf(u00, f00.x, fmaf(u10, f10.x, fmaf(u01, f01.x, fmaf(u11, f11.x, acc0))));
        acc1 = fmaf(u00, f00.y, fmaf(u10, f10.y, fmaf(u01, f01.y, fmaf(u11, f11.y, acc1))));
    }

    acc0 += __shfl_xor_sync(0xffffffffu, acc0, 16);
    acc1 += __shfl_xor_sync(0xffffffffu, acc1, 16);
    if (hw == 0)
        ((__half2*)out)[(size_t)t * 128 + h * 16 + cl] = __floats2half2_rn(acc0, acc1);
}

// ---------------------------------------------------------------------------
extern "C" void kernel_launch(void* const* d_in, const int* in_sizes, int n_in,
                              void* d_out, int out_size)
{
    const float* src    = (const float*)d_in[0];
    const float* pos    = (const float*)d_in[1];
    const float* refp   = (const float*)d_in[2];
    const float* g1     = (const float*)d_in[5];
    const float* beta1  = (const float*)d_in[6];
    const float* w_off  = (const float*)d_in[7];
    const float* b_off  = (const float*)d_in[8];
    const float* w_attn = (const float*)d_in[9];
    const float* b_attn = (const float*)d_in[10];
    const float* w_val  = (const float*)d_in[11];
    const float* b_val  = (const float*)d_in[12];
    const float* w_out  = (const float*)d_in[13];
    const float* b_out  = (const float*)d_in[14];
    const float* g2     = (const float*)d_in[15];
    const float* beta2  = (const float*)d_in[16];
    const float* w_fc1  = (const float*)d_in[17];
    const float* b_fc1  = (const float*)d_in[18];
    const float* w_fc2  = (const float*)d_in[19];
    const float* b_fc2  = (const float*)d_in[20];
    float* out = (float*)d_out;

    __half *p_xln, *p_q, *p_val, *p_samp, *p_y, *p_h;
    float *p_oa, *p_src2;
    __half *p_wvalT, *p_woaT, *p_woutT, *p_wfc1T, *p_wfc2T;
    cudaGetSymbolAddress((void**)&p_xln,  g_xln_h);
    cudaGetSymbolAddress((void**)&p_q,    g_q_h);
    cudaGetSymbolAddress((void**)&p_val,  g_val_h);
    cudaGetSymbolAddress((void**)&p_samp, g_samp_h);
    cudaGetSymbolAddress((void**)&p_y,    g_y_h);
    cudaGetSymbolAddress((void**)&p_h,    g_h_h);
    cudaGetSymbolAddress((void**)&p_oa,   g_oa);
    cudaGetSymbolAddress((void**)&p_src2, g_src2);
    cudaGetSymbolAddress((void**)&p_wvalT, g_wvalT);
    cudaGetSymbolAddress((void**)&p_woaT,  g_woaT);
    cudaGetSymbolAddress((void**)&p_woutT, g_woutT);
    cudaGetSymbolAddress((void**)&p_wfc1T, g_wfc1T);
    cudaGetSymbolAddress((void**)&p_wfc2T, g_wfc2T);

    cudaFuncSetAttribute(gemm_ln, cudaFuncAttributeMaxDynamicSharedMemorySize, GL_SMEM);

    const int M = TTOK;

    // 0) weight transposes (one launch)
    TDescs td;
    td.d[0] = {w_val,  p_wvalT,            256, 256};
    td.d[1] = {w_off,  p_woaT,             256, 256};
    td.d[2] = {w_attn, p_woaT + 256 * 256, 256, 128};
    td.d[3] = {w_out,  p_woutT,            256, 256};
    td.d[4] = {w_fc1,  p_wfc1T,            256, MLPD};
    td.d[5] = {w_fc2,  p_wfc2T,            MLPD, 256};
    transpose_all<<<dim3(32, 32, 6), dim3(32, 8)>>>(td);

    // 1) LN1 + q = ln(src) + pos
    ln_kernel<<<TTOK / 8, 256>>>(src, pos, g1, beta1, p_xln, p_q);

    // 2) fused: val = xln @ w_val ; oa = q @ [w_off|w_attn]
    dual_gemm<<<dim3(5, M / 128), 256>>>(p_xln, p_q, p_wvalT, p_woaT,
                                         b_val, b_off, b_attn, p_val, p_oa);

    // 3) deformable sampling (fused softmax) — issue-optimized
    msda_kernel<<<TTOK, 256>>>(p_val, p_oa, refp, p_samp);

    // 4) src2 = src + samp @ w_out + b_out; y = LN2(src2)   (fused)
    gemm_ln<<<dim3(1, M / 128), 256, GL_SMEM>>>(p_samp, p_woutT, b_out, src,
                                                g2, beta2, p_src2, p_y);

    // 5) h = relu(y @ w_fc1 + b_fc1)
    hgemm<true, false, __half><<<dim3(MLPD / 128, M / 128), 256>>>(p_y, p_wfc1T, b_fc1, nullptr, p_h, M, MLPD, 256);

    // 6) out = src2 + h @ w_fc2 + b_fc2
    hgemm<false, true, float><<<dim3(2, M / 128), 256>>>(p_h, p_wfc2T, b_fc2, p_src2, out, M, 256, 1024);
}